// round 14
// baseline (speedup 1.0000x reference)
#include <cuda_runtime.h>
#include <cuda_bf16.h>
#include <math.h>
#include <stdint.h>

#define BATCH 8
#define DM    256
#define LSEQ  8192
#define NF    8192      /* complex FFT size (for 16384-point real FFT) */
#define FFT_THREADS 1024
#define BKP   40        /* padded bf16 row stride in GEMM smem tiles */
#define FFT_SMEM ((NF + NF / 16) * 8)   /* padded float2 array: 69632 B */

/* ---------------- scratch (device globals; no allocation allowed) ---------------- */
__device__ float2 g_tw8k[4096];                 /* exp(-2pi i j/8192), j<4096   */
__device__ float2 g_u16[8193];                  /* exp(-2pi i k/16384), k<=8192 */
__device__ float  g_sactT[64 * LSEQ];           /* silu(t*W1+b1)^T [64][L]     */
__device__ float  g_h[DM * LSEQ];               /* implicit filter [D][L]      */
__device__ float2 g_Hf[DM * 8193];              /* rfft16384(filter)/16384     */
__device__ __nv_bfloat16 g_W1hi[768 * 256];
__device__ __nv_bfloat16 g_W1lo[768 * 256];
__device__ __nv_bfloat16 g_W2hi[256 * 256];
__device__ __nv_bfloat16 g_W2lo[256 * 256];
__device__ float  g_v [(size_t)BATCH * DM * LSEQ];
__device__ float  g_g0[(size_t)BATCH * DM * LSEQ];
__device__ float  g_g1[(size_t)BATCH * DM * LSEQ];
__device__ float  g_gatedT[(size_t)BATCH * DM * LSEQ];  /* gated, [b][d][l] */

/* ---------------- helpers ---------------- */
__device__ __forceinline__ float2 cmul(float2 a, float2 b) {
    return make_float2(a.x * b.x - a.y * b.y, a.x * b.y + a.y * b.x);
}
__device__ __forceinline__ float2 cmulc(float2 a, float2 w) { /* a * conj(w) */
    return make_float2(a.x * w.x + a.y * w.y, a.y * w.x - a.x * w.y);
}
/* padded smem index: 1 float2 pad per 16 -> low-stride stages drop 4-way conflicts */
__device__ __forceinline__ int IDX(int n) { return n + (n >> 4); }

/* storage position of frequency bin k after radix-4(x6)+radix-2 DIF */
__device__ __forceinline__ int perm13(int k) {
    unsigned v = __brev((unsigned)k) >> 19;
    unsigned w = v >> 1;
    unsigned r = ((w & 0xAAAu) >> 1) | ((w & 0x555u) << 1);
    return (int)((r << 1) | (v & 1u));
}

/* ---------------- table init (idempotent, runs every launch) ---------------- */
__global__ void init_tables_kernel() {
    int i = blockIdx.x * blockDim.x + threadIdx.x;
    if (i < 4096) {
        double a = -2.0 * M_PI * (double)i / 8192.0;
        double s, c; sincos(a, &s, &c);
        g_tw8k[i] = make_float2((float)c, (float)s);
    }
    if (i < 8193) {
        double a = -2.0 * M_PI * (double)i / 16384.0;
        double s, c; sincos(a, &s, &c);
        g_u16[i] = make_float2((float)c, (float)s);
    }
}

/* ---------------- fp32 -> bf16 hi/lo split (weights only) ---------------- */
__global__ void split_bf16_kernel(const float* __restrict__ in,
                                  __nv_bfloat16* __restrict__ hi,
                                  __nv_bfloat16* __restrict__ lo, int n) {
    int i = 4 * (blockIdx.x * blockDim.x + threadIdx.x);
    if (i < n) {
        float4 v = *(const float4*)&in[i];
        __nv_bfloat16 h0 = __float2bfloat16_rn(v.x);
        __nv_bfloat16 h1 = __float2bfloat16_rn(v.y);
        __nv_bfloat16 h2 = __float2bfloat16_rn(v.z);
        __nv_bfloat16 h3 = __float2bfloat16_rn(v.w);
        __nv_bfloat162 ph01; ph01.x = h0; ph01.y = h1;
        __nv_bfloat162 ph23; ph23.x = h2; ph23.y = h3;
        *(__nv_bfloat162*)&hi[i]     = ph01;
        *(__nv_bfloat162*)&hi[i + 2] = ph23;
        __nv_bfloat162 pl01, pl23;
        pl01.x = __float2bfloat16_rn(v.x - __bfloat162float(h0));
        pl01.y = __float2bfloat16_rn(v.y - __bfloat162float(h1));
        pl23.x = __float2bfloat16_rn(v.z - __bfloat162float(h2));
        pl23.y = __float2bfloat16_rn(v.w - __bfloat162float(h3));
        *(__nv_bfloat162*)&lo[i]     = pl01;
        *(__nv_bfloat162*)&lo[i + 2] = pl23;
    }
}

/* ---------------- sactT[m][l] = silu(t[l]*W1[m] + b1[m]) ---------------- */
__global__ void sact_kernel(const float* __restrict__ t, const float* __restrict__ W1,
                            const float* __restrict__ b1) {
    int idx = blockIdx.x * blockDim.x + threadIdx.x;
    if (idx < 64 * LSEQ) {
        int m = idx >> 13, l = idx & (LSEQ - 1);
        float z = t[l] * W1[m] + b1[m];
        g_sactT[idx] = z / (1.0f + expf(-z));
    }
}

/* ---------------- h[d][l] = sum_m sactT[m][l]*W2[d][m] + b2[d] ---------------- */
__global__ void hmix_kernel(const float* __restrict__ W2, const float* __restrict__ b2) {
    __shared__ float s[64][129];
    int l0 = blockIdx.x * 128;
    int tid = threadIdx.x; /* 128 */
    for (int m = 0; m < 64; m++) s[m][tid] = g_sactT[m * LSEQ + l0 + tid];
    __syncthreads();
    for (int d0 = 0; d0 < 256; d0 += 4) {
        float a0 = b2[d0 + 0], a1 = b2[d0 + 1], a2 = b2[d0 + 2], a3 = b2[d0 + 3];
        #pragma unroll
        for (int m = 0; m < 64; m++) {
            float sv = s[m][tid];
            a0 += sv * __ldg(&W2[(d0 + 0) * 64 + m]);
            a1 += sv * __ldg(&W2[(d0 + 1) * 64 + m]);
            a2 += sv * __ldg(&W2[(d0 + 2) * 64 + m]);
            a3 += sv * __ldg(&W2[(d0 + 3) * 64 + m]);
        }
        g_h[(size_t)(d0 + 0) * LSEQ + l0 + tid] = a0;
        g_h[(size_t)(d0 + 1) * LSEQ + l0 + tid] = a1;
        g_h[(size_t)(d0 + 2) * LSEQ + l0 + tid] = a2;
        g_h[(size_t)(d0 + 3) * LSEQ + l0 + tid] = a3;
    }
}

/* -------- in-smem radix-4 FFT (8192-pt complex), 6xR4 + 1xR2, padded layout ----- */
__device__ __forceinline__ void fft8k_dif(float2* zs, int tid) {
    #pragma unroll
    for (int ls = 11; ls >= 1; ls -= 2) {
        int s = 1 << ls;
        for (int j = tid; j < 2048; j += FFT_THREADS) {
            int o = j & (s - 1);
            int base = ((j >> ls) << (ls + 2)) + o;
            int i0 = IDX(base), i1 = IDX(base + s), i2 = IDX(base + 2 * s), i3 = IDX(base + 3 * s);
            float2 a = zs[i0], b = zs[i1], c = zs[i2], d = zs[i3];
            float2 t0 = make_float2(a.x + c.x, a.y + c.y);
            float2 t1 = make_float2(a.x - c.x, a.y - c.y);
            float2 t2 = make_float2(b.x + d.x, b.y + d.y);
            float2 t3 = make_float2(b.y - d.y, -(b.x - d.x));   /* -i(b-d) */
            int twi = o << (11 - ls);
            float2 w1 = g_tw8k[twi];
            float2 w2 = g_tw8k[2 * twi];
            float2 w3 = cmul(w1, w2);
            zs[i0] = make_float2(t0.x + t2.x, t0.y + t2.y);
            zs[i1] = cmul(make_float2(t1.x + t3.x, t1.y + t3.y), w1);
            zs[i2] = cmul(make_float2(t0.x - t2.x, t0.y - t2.y), w2);
            zs[i3] = cmul(make_float2(t1.x - t3.x, t1.y - t3.y), w3);
        }
        __syncthreads();
    }
    for (int j = tid; j < 4096; j += FFT_THREADS) {
        int i0 = IDX(2 * j);     /* 2j even -> 2j+1 in same pad block */
        float2 a = zs[i0], b = zs[i0 + 1];
        zs[i0]     = make_float2(a.x + b.x, a.y + b.y);
        zs[i0 + 1] = make_float2(a.x - b.x, a.y - b.y);
    }
    __syncthreads();
}
__device__ __forceinline__ void fft8k_dit_inv(float2* zs, int tid) {
    for (int j = tid; j < 4096; j += FFT_THREADS) {
        int i0 = IDX(2 * j);
        float2 a = zs[i0], b = zs[i0 + 1];
        zs[i0]     = make_float2(a.x + b.x, a.y + b.y);
        zs[i0 + 1] = make_float2(a.x - b.x, a.y - b.y);
    }
    __syncthreads();
    #pragma unroll
    for (int ls = 1; ls <= 11; ls += 2) {
        int s = 1 << ls;
        for (int j = tid; j < 2048; j += FFT_THREADS) {
            int o = j & (s - 1);
            int base = ((j >> ls) << (ls + 2)) + o;
            int i0 = IDX(base), i1 = IDX(base + s), i2 = IDX(base + 2 * s), i3 = IDX(base + 3 * s);
            float2 A = zs[i0], B = zs[i1], C = zs[i2], D = zs[i3];
            int twi = o << (11 - ls);
            float2 w1 = g_tw8k[twi];
            float2 w2 = g_tw8k[2 * twi];
            float2 w3 = cmul(w1, w2);
            float2 u1 = cmulc(B, w1);
            float2 u2 = cmulc(C, w2);
            float2 u3 = cmulc(D, w3);
            float2 s0 = make_float2(A.x + u2.x, A.y + u2.y);
            float2 s1 = make_float2(A.x - u2.x, A.y - u2.y);
            float2 s2 = make_float2(u1.x + u3.x, u1.y + u3.y);
            float2 s3 = make_float2(-(u1.y - u3.y), u1.x - u3.x); /* i(u1-u3) */
            zs[i0] = make_float2(s0.x + s2.x, s0.y + s2.y);
            zs[i1] = make_float2(s1.x + s3.x, s1.y + s3.y);
            zs[i2] = make_float2(s0.x - s2.x, s0.y - s2.y);
            zs[i3] = make_float2(s1.x - s3.x, s1.y - s3.y);
        }
        __syncthreads();
    }
}

/* ---------------- filter FFT (1/16384 folded into Hf) ---------------- */
__global__ void hf_kernel() {
    extern __shared__ float2 zs[];
    int d = blockIdx.x;
    int tid = threadIdx.x;
    const float sc = 1.0f / (float)NF;
    const float2* hr = (const float2*)(g_h + (size_t)d * LSEQ);
    for (int n = tid; n < 4096; n += FFT_THREADS) zs[IDX(n)] = hr[n];
    for (int n = 4096 + tid; n < NF; n += FFT_THREADS) zs[IDX(n)] = make_float2(0.f, 0.f);
    __syncthreads();
    fft8k_dif(zs, tid);
    float2* Hf = g_Hf + (size_t)d * 8193;
    for (int k = tid; k <= 4096; k += FFT_THREADS) {
        if (k == 0) {
            float2 Z0 = zs[0];
            Hf[0]    = make_float2(sc * (Z0.x + Z0.y), 0.f);
            Hf[8192] = make_float2(sc * (Z0.x - Z0.y), 0.f);
        } else if (k == 4096) {
            float2 Z = zs[1]; /* perm13(4096)=1, IDX(1)=1 */
            Hf[4096] = make_float2(sc * Z.x, -sc * Z.y);
        } else {
            float2 Za = zs[IDX(perm13(k))], Zb = zs[IDX(perm13(8192 - k))];
            float2 Xe = make_float2(0.5f * (Za.x + Zb.x), 0.5f * (Za.y - Zb.y));
            float2 dd = make_float2(Za.x - Zb.x, Za.y + Zb.y);
            float2 Xo = make_float2(0.5f * dd.y, -0.5f * dd.x);
            float2 w  = g_u16[k];
            float2 wXo = cmul(w, Xo);
            Hf[k]        = make_float2(sc * (Xe.x + wXo.x), sc * (Xe.y + wXo.y));
            Hf[8192 - k] = make_float2(sc * (Xe.x - wXo.x), -sc * (Xe.y - wXo.y));
        }
    }
}

/* -- conv FFT + fused gating: gatedT[b][d][l] = irfft(rfft(v)*Hf)[:L] * c0 * c1 -- */
__global__ void conv_fft_kernel(const float* __restrict__ v,
                                const float* __restrict__ g0r, const float* __restrict__ g1r,
                                const float* __restrict__ w0, const float* __restrict__ b0,
                                const float* __restrict__ w1, const float* __restrict__ b1,
                                float* __restrict__ gatedT) {
    extern __shared__ float2 zs[];
    int bd = blockIdx.x;
    int d = bd & (DM - 1);
    int tid = threadIdx.x;
    const float2* vr = (const float2*)(v + (size_t)bd * LSEQ);
    for (int n = tid; n < 4096; n += FFT_THREADS) zs[IDX(n)] = vr[n];
    for (int n = 4096 + tid; n < NF; n += FFT_THREADS) zs[IDX(n)] = make_float2(0.f, 0.f);
    __syncthreads();
    fft8k_dif(zs, tid);
    const float2* Hf = g_Hf + (size_t)d * 8193;
    for (int k = tid; k <= 4096; k += FFT_THREADS) {
        if (k == 0) {
            float2 Z0 = zs[0];
            float X0 = Z0.x + Z0.y, XN = Z0.x - Z0.y;
            float2 H0 = Hf[0], HN = Hf[8192];
            float2 P0 = make_float2(X0 * H0.x, X0 * H0.y);
            float2 PN = make_float2(XN * HN.x, XN * HN.y);
            float2 Xe2 = make_float2(0.5f * (P0.x + PN.x), 0.5f * (P0.y - PN.y));
            float2 Xo2 = make_float2(0.5f * (P0.x - PN.x), 0.5f * (P0.y + PN.y));
            zs[0] = make_float2(Xe2.x - Xo2.y, Xe2.y + Xo2.x);
        } else if (k == 4096) {
            float2 Z = zs[1];
            float2 H = Hf[4096];
            zs[1] = make_float2(Z.x * H.x + Z.y * H.y, Z.y * H.x - Z.x * H.y);
        } else {
            int p1 = IDX(perm13(k)), p2 = IDX(perm13(8192 - k));
            float2 Za = zs[p1], Zb = zs[p2];
            float2 Xe = make_float2(0.5f * (Za.x + Zb.x), 0.5f * (Za.y - Zb.y));
            float2 dd = make_float2(Za.x - Zb.x, Za.y + Zb.y);
            float2 Xo = make_float2(0.5f * dd.y, -0.5f * dd.x);
            float2 w  = g_u16[k];
            float2 wXo = cmul(w, Xo);
            float2 Xp = make_float2(Xe.x + wXo.x, Xe.y + wXo.y);
            float2 Xm = make_float2(Xe.x - wXo.x, Xe.y - wXo.y);
            float2 Hk = Hf[k], Hn = Hf[8192 - k];
            float2 P1 = cmul(Xp, Hk);
            float2 Q  = cmul(Xm, make_float2(Hn.x, -Hn.y));
            float2 Xe2 = make_float2(0.5f * (P1.x + Q.x), 0.5f * (P1.y + Q.y));
            float2 pmq = make_float2(P1.x - Q.x, P1.y - Q.y);
            float2 Xo2 = cmul(make_float2(w.x, -w.y), pmq);
            Xo2.x *= 0.5f; Xo2.y *= 0.5f;
            zs[p1] = make_float2(Xe2.x - Xo2.y, Xe2.y + Xo2.x);
            zs[p2] = make_float2(Xe2.x + Xo2.y, Xo2.x - Xe2.y);
        }
    }
    __syncthreads();
    fft8k_dit_inv(zs, tid);

    /* fused dwconv(K=3) gating epilogue. Each thread owns 8 contiguous l.        */
    {
        int l0c = tid * 8;
        size_t rowoff = (size_t)bd * LSEQ + l0c;
        const float* g0p = g0r + rowoff;
        const float* g1p = g1r + rowoff;
        float G0[10], G1[10];
        #pragma unroll
        for (int j = 0; j < 2; j++) {
            float4 q0 = *(const float4*)&g0p[j * 4];
            float4 q1 = *(const float4*)&g1p[j * 4];
            G0[1 + j * 4] = q0.x; G0[2 + j * 4] = q0.y; G0[3 + j * 4] = q0.z; G0[4 + j * 4] = q0.w;
            G1[1 + j * 4] = q1.x; G1[2 + j * 4] = q1.y; G1[3 + j * 4] = q1.z; G1[4 + j * 4] = q1.w;
        }
        G0[0] = (l0c > 0) ? g0p[-1] : 0.f;
        G1[0] = (l0c > 0) ? g1p[-1] : 0.f;
        G0[9] = (l0c + 8 < LSEQ) ? g0p[8] : 0.f;
        G1[9] = (l0c + 8 < LSEQ) ? g1p[8] : 0.f;
        float w00 = w0[3 * d], w01 = w0[3 * d + 1], w02 = w0[3 * d + 2], cb0 = b0[d];
        float w10 = w1[3 * d], w11 = w1[3 * d + 1], w12 = w1[3 * d + 2], cb1 = b1[d];
        float Y[8];
        int zb = IDX(tid * 4);   /* 4 consecutive float2, no pad boundary inside */
        #pragma unroll
        for (int j = 0; j < 4; j++) {
            float2 yv = zs[zb + j];
            Y[2 * j] = yv.x; Y[2 * j + 1] = yv.y;
        }
        float O[8];
        #pragma unroll
        for (int i = 0; i < 8; i++) {
            float c0v = w00 * G0[i] + w01 * G0[i + 1] + w02 * G0[i + 2] + cb0;
            float c1v = w10 * G1[i] + w11 * G1[i + 1] + w12 * G1[i + 2] + cb1;
            O[i] = Y[i] * c0v * c1v;
        }
        float* op = gatedT + rowoff;
        *(float4*)&op[0] = make_float4(O[0], O[1], O[2], O[3]);
        *(float4*)&op[4] = make_float4(O[4], O[5], O[6], O[7]);
    }
}

/* ---------------- bf16 split-precision tensor-core GEMM ------------------------ */
__device__ __forceinline__ void mma_bf16(float c[4], const unsigned a[4],
                                         unsigned b0, unsigned b1) {
    asm volatile(
        "mma.sync.aligned.m16n8k16.row.col.f32.bf16.bf16.f32 "
        "{%0,%1,%2,%3}, {%4,%5,%6,%7}, {%8,%9}, {%0,%1,%2,%3};\n"
        : "+f"(c[0]), "+f"(c[1]), "+f"(c[2]), "+f"(c[3])
        : "r"(a[0]), "r"(a[1]), "r"(a[2]), "r"(a[3]), "r"(b0), "r"(b1));
}

/* GEMM1: A row-major fp32 (hi/lo split in staging), transposed epilogue to       */
/* v/g0/g1 in [b][d][l].  128x128 CTA, BK=32, 8 warps, single-buffer prefetch.    */
__global__ void __launch_bounds__(256) mma_gemm_kernel(
    const float* __restrict__ A,
    const __nv_bfloat16* __restrict__ Bhi, const __nv_bfloat16* __restrict__ Blo,
    const float* __restrict__ bias,
    float* __restrict__ C0p, float* __restrict__ C1p, float* __restrict__ C2p,
    int M, int N, int K) {
    extern __shared__ char smraw[];
    __nv_bfloat16* sAhi = (__nv_bfloat16*)smraw;            /* [128][BKP] */
    __nv_bfloat16* sAlo = sAhi + 128 * BKP;
    __nv_bfloat16* sBhi = sAlo + 128 * BKP;
    __nv_bfloat16* sBlo = sBhi + 128 * BKP;
    float* ep = (float*)smraw;                              /* [128][132] staging */

    int tid = threadIdx.x;
    int warp = tid >> 5, lane = tid & 31;
    int gid = lane >> 2, tig = lane & 3;
    int warp_m = (warp >> 1) * 32;
    int warp_n = (warp & 1) * 64;
    int m0 = blockIdx.y * 128, n0 = blockIdx.x * 128;
    const float4* gA = (const float4*)A;
    const uint4* gBh = (const uint4*)Bhi;
    const uint4* gBl = (const uint4*)Blo;
    int ldvA = K >> 2;
    int ldvB = K >> 3;

    float acc[2][8][4];
    #pragma unroll
    for (int mt = 0; mt < 2; mt++)
        #pragma unroll
        for (int nt = 0; nt < 8; nt++)
            #pragma unroll
            for (int q = 0; q < 4; q++) acc[mt][nt][q] = 0.f;

    float4 rA[4];
    uint4  rBh[2], rBl[2];

    auto load_tile = [&](int k0) {
        int kqa = k0 >> 2, kqb = k0 >> 3;
        #pragma unroll
        for (int i = 0; i < 4; i++) {
            int idx = tid + i * 256;
            int row = idx >> 3, kq = idx & 7;
            rA[i] = gA[(size_t)(m0 + row) * ldvA + kqa + kq];
        }
        #pragma unroll
        for (int i = 0; i < 2; i++) {
            int idx = tid + i * 256;
            int row = idx >> 2, kq = idx & 3;
            rBh[i] = gBh[(size_t)(n0 + row) * ldvB + kqb + kq];
            rBl[i] = gBl[(size_t)(n0 + row) * ldvB + kqb + kq];
        }
    };
    auto store_tile = [&]() {
        #pragma unroll
        for (int i = 0; i < 4; i++) {
            int idx = tid + i * 256;
            int row = idx >> 3, kq = idx & 7;
            float4 v = rA[i];
            __nv_bfloat16 h0 = __float2bfloat16_rn(v.x);
            __nv_bfloat16 h1 = __float2bfloat16_rn(v.y);
            __nv_bfloat16 h2 = __float2bfloat16_rn(v.z);
            __nv_bfloat16 h3 = __float2bfloat16_rn(v.w);
            __nv_bfloat162 ph01; ph01.x = h0; ph01.y = h1;
            __nv_bfloat162 ph23; ph23.x = h2; ph23.y = h3;
            int off = row * BKP + kq * 4;
            *(__nv_bfloat162*)&sAhi[off]     = ph01;
            *(__nv_bfloat162*)&sAhi[off + 2] = ph23;
            __nv_bfloat162 pl01, pl23;
            pl01.x = __float2bfloat16_rn(v.x - __bfloat162float(h0));
            pl01.y = __float2bfloat16_rn(v.y - __bfloat162float(h1));
            pl23.x = __float2bfloat16_rn(v.z - __bfloat162float(h2));
            pl23.y = __float2bfloat16_rn(v.w - __bfloat162float(h3));
            *(__nv_bfloat162*)&sAlo[off]     = pl01;
            *(__nv_bfloat162*)&sAlo[off + 2] = pl23;
        }
        #pragma unroll
        for (int i = 0; i < 2; i++) {
            int idx = tid + i * 256;
            int row = idx >> 2, kq = idx & 3;
            *(uint4*)&sBhi[row * BKP + kq * 8] = rBh[i];
            *(uint4*)&sBlo[row * BKP + kq * 8] = rBl[i];
        }
    };

    load_tile(0);
    for (int k0 = 0; k0 < K; k0 += 32) {
        __syncthreads();
        store_tile();
        __syncthreads();
        if (k0 + 32 < K) load_tile(k0 + 32);
        #pragma unroll
        for (int k16 = 0; k16 < 32; k16 += 16) {
            unsigned ah[2][4], al[2][4];
            #pragma unroll
            for (int mt = 0; mt < 2; mt++) {
                int base = (warp_m + mt * 16 + gid) * BKP + k16 + 2 * tig;
                ah[mt][0] = *(const unsigned*)&sAhi[base];
                ah[mt][1] = *(const unsigned*)&sAhi[base + 8 * BKP];
                ah[mt][2] = *(const unsigned*)&sAhi[base + 8];
                ah[mt][3] = *(const unsigned*)&sAhi[base + 8 * BKP + 8];
                al[mt][0] = *(const unsigned*)&sAlo[base];
                al[mt][1] = *(const unsigned*)&sAlo[base + 8 * BKP];
                al[mt][2] = *(const unsigned*)&sAlo[base + 8];
                al[mt][3] = *(const unsigned*)&sAlo[base + 8 * BKP + 8];
            }
            #pragma unroll
            for (int nt = 0; nt < 8; nt++) {
                int cbase = (warp_n + nt * 8 + gid) * BKP + k16 + 2 * tig;
                unsigned bh0 = *(const unsigned*)&sBhi[cbase];
                unsigned bh1 = *(const unsigned*)&sBhi[cbase + 8];
                unsigned bl0 = *(const unsigned*)&sBlo[cbase];
                unsigned bl1 = *(const unsigned*)&sBlo[cbase + 8];
                #pragma unroll
                for (int mt = 0; mt < 2; mt++) {
                    mma_bf16(acc[mt][nt], ah[mt], bh0, bh1);
                    mma_bf16(acc[mt][nt], ah[mt], bl0, bl1);
                    mma_bf16(acc[mt][nt], al[mt], bh0, bh1);
                }
            }
        }
    }

    /* transposed epilogue -> v/g0/g1 in [b][d][l] layout, bias folded in */
    __syncthreads();
    #pragma unroll
    for (int mt = 0; mt < 2; mt++) {
        #pragma unroll
        for (int nt = 0; nt < 8; nt++) {
            int rl = warp_m + mt * 16 + gid;
            int cl = warp_n + nt * 8 + 2 * tig;
            ep[(size_t)cl * 132 + rl]           = acc[mt][nt][0];
            ep[(size_t)(cl + 1) * 132 + rl]     = acc[mt][nt][1];
            ep[(size_t)cl * 132 + rl + 8]       = acc[mt][nt][2];
            ep[(size_t)(cl + 1) * 132 + rl + 8] = acc[mt][nt][3];
        }
    }
    __syncthreads();
    int b = m0 >> 13;
    int l0 = m0 & (LSEQ - 1);
    int branch = n0 >> 8;
    int cc0 = n0 & 255;
    float* outp = (branch == 0) ? C0p : ((branch == 1) ? C1p : C2p);
    for (int i = tid; i < 16384; i += 256) {
        int c = i >> 7, l = i & 127;
        outp[((size_t)b * DM + cc0 + c) * LSEQ + l0 + l] = ep[c * 132 + l] + bias[n0 + c];
    }
}

/* GEMM2 (TRANSA): A stored k-major as At[b][k=d][l].  C[M][N] row-major + bias.  */
__global__ void __launch_bounds__(256) mma_gemm_ta_kernel(
    const float* __restrict__ At,
    const __nv_bfloat16* __restrict__ Bhi, const __nv_bfloat16* __restrict__ Blo,
    const float* __restrict__ bias, float* __restrict__ C,
    int M, int N, int K) {
    extern __shared__ char smraw[];
    __nv_bfloat16* sAhi = (__nv_bfloat16*)smraw;            /* [128][BKP] */
    __nv_bfloat16* sAlo = sAhi + 128 * BKP;
    __nv_bfloat16* sBhi = sAlo + 128 * BKP;
    __nv_bfloat16* sBlo = sBhi + 128 * BKP;
    float* sT = (float*)(smraw + 4 * 128 * BKP * 2);        /* [32][132] fp32 */

    int tid = threadIdx.x;
    int warp = tid >> 5, lane = tid & 31;
    int gid = lane >> 2, tig = lane & 3;
    int warp_m = (warp >> 1) * 32;
    int warp_n = (warp & 1) * 64;
    int m0 = blockIdx.y * 128, n0 = blockIdx.x * 128;
    int b = m0 >> 13, l0 = m0 & (LSEQ - 1);
    const uint4* gBh = (const uint4*)Bhi;
    const uint4* gBl = (const uint4*)Blo;
    int ldvB = K >> 3;

    float acc[2][8][4];
    #pragma unroll
    for (int mt = 0; mt < 2; mt++)
        #pragma unroll
        for (int nt = 0; nt < 8; nt++)
            #pragma unroll
            for (int q = 0; q < 4; q++) acc[mt][nt][q] = 0.f;

    float4 rA[4];
    uint4  rBh[2], rBl[2];
    int kkA = tid >> 3, qA = tid & 7;    /* 32 k-rows x 8 threads/row */

    auto load_tile = [&](int k0) {
        const float4* pA = (const float4*)(At + ((size_t)b * DM + k0 + kkA) * LSEQ + l0);
        #pragma unroll
        for (int j = 0; j < 4; j++) rA[j] = pA[qA * 4 + j];
        int kqb = k0 >> 3;
        #pragma unroll
        for (int i = 0; i < 2; i++) {
            int idx = tid + i * 256;
            int row = idx >> 2, kq = idx & 3;
            rBh[i] = gBh[(size_t)(n0 + row) * ldvB + kqb + kq];
            rBl[i] = gBl[(size_t)(n0 + row) * ldvB + kqb + kq];
        }
    };
    auto store_tile = [&]() {
        #pragma unroll
        for (int j = 0; j < 4; j++)
            *(float4*)&sT[kkA * 132 + qA * 16 + j * 4] = rA[j];
        #pragma unroll
        for (int i = 0; i < 2; i++) {
            int idx = tid + i * 256;
            int row = idx >> 2, kq = idx & 3;
            *(uint4*)&sBhi[row * BKP + kq * 8] = rBh[i];
            *(uint4*)&sBlo[row * BKP + kq * 8] = rBl[i];
        }
    };
    auto convert = [&]() {
        int m = tid >> 1, kh = (tid & 1) * 16;
        #pragma unroll
        for (int j = 0; j < 16; j += 2) {
            float v0 = sT[(kh + j) * 132 + m];
            float v1 = sT[(kh + j + 1) * 132 + m];
            __nv_bfloat16 h0 = __float2bfloat16_rn(v0);
            __nv_bfloat16 h1 = __float2bfloat16_rn(v1);
            __nv_bfloat162 ph; ph.x = h0; ph.y = h1;
            *(__nv_bfloat162*)&sAhi[m * BKP + kh + j] = ph;
            __nv_bfloat162 pl;
            pl.x = __float2bfloat16_rn(v0 - __bfloat162float(h0));
            pl.y = __float2bfloat16_rn(v1 - __bfloat162float(h1));
            *(__nv_bfloat162*)&sAlo[m * BKP + kh + j] = pl;
        }
    };

    load_tile(0);
    for (int k0 = 0; k0 < K; k0 += 32) {
        __syncthreads();           /* prev compute done reading sA/sB */
        store_tile();
        __syncthreads();           /* sT/sB visible */
        convert();
        if (k0 + 32 < K) load_tile(k0 + 32);
        __syncthreads();           /* sA visible */
        #pragma unroll
        for (int k16 = 0; k16 < 32; k16 += 16) {
            unsigned ah[2][4], al[2][4];
            #pragma unroll
            for (int mt = 0; mt < 2; mt++) {
                int base = (warp_m + mt * 16 + gid) * BKP + k16 + 2 * tig;
                ah[mt][0] = *(const unsigned*)&sAhi[base];
                ah[mt][1] = *(const unsigned*)&sAhi[base + 8 * BKP];
                ah[mt][2] = *(const unsigned*)&sAhi[base + 8];
                ah[mt][3] = *(const unsigned*)&sAhi[base + 8 * BKP + 8];
                al[mt][0] = *(const unsigned*)&sAlo[base];
                al[mt][1] = *(const unsigned*)&sAlo[base + 8 * BKP];
                al[mt][2] = *(const unsigned*)&sAlo[base + 8];
                al[mt][3] = *(const unsigned*)&sAlo[base + 8 * BKP + 8];
            }
            #pragma unroll
            for (int nt = 0; nt < 8; nt++) {
                int cbase = (warp_n + nt * 8 + gid) * BKP + k16 + 2 * tig;
                unsigned bh0 = *(const unsigned*)&sBhi[cbase];
                unsigned bh1 = *(const unsigned*)&sBhi[cbase + 8];
                unsigned bl0 = *(const unsigned*)&sBlo[cbase];
                unsigned bl1 = *(const unsigned*)&sBlo[cbase + 8];
                #pragma unroll
                for (int mt = 0; mt < 2; mt++) {
                    mma_bf16(acc[mt][nt], ah[mt], bh0, bh1);
                    mma_bf16(acc[mt][nt], ah[mt], bl0, bl1);
                    mma_bf16(acc[mt][nt], al[mt], bh0, bh1);
                }
            }
        }
    }

    #pragma unroll
    for (int mt = 0; mt < 2; mt++) {
        #pragma unroll
        for (int nt = 0; nt < 8; nt++) {
            int r = m0 + warp_m + mt * 16 + gid;
            int c = n0 + warp_n + nt * 8 + 2 * tig;
            float b0v = bias[c], b1v = bias[c + 1];
            float2 w0v = make_float2(acc[mt][nt][0] + b0v, acc[mt][nt][1] + b1v);
            float2 w1v = make_float2(acc[mt][nt][2] + b0v, acc[mt][nt][3] + b1v);
            *(float2*)&C[(size_t)r * N + c] = w0v;
            *(float2*)&C[(size_t)(r + 8) * N + c] = w1v;
        }
    }
}

/* ---------------- launch ---------------- */
extern "C" void kernel_launch(void* const* d_in, const int* in_sizes, int n_in,
                              void* d_out, int out_size) {
    const float* x       = (const float*)d_in[0];
    const float* in_W    = (const float*)d_in[1];
    const float* in_b    = (const float*)d_in[2];
    const float* conv0_W = (const float*)d_in[3];
    const float* conv0_b = (const float*)d_in[4];
    const float* conv1_W = (const float*)d_in[5];
    const float* conv1_b = (const float*)d_in[6];
    const float* mlp_W1  = (const float*)d_in[7];
    const float* mlp_b1  = (const float*)d_in[8];
    const float* mlp_W2  = (const float*)d_in[9];
    const float* mlp_b2  = (const float*)d_in[10];
    const float* out_W   = (const float*)d_in[11];
    const float* out_b   = (const float*)d_in[12];
    const float* t       = (const float*)d_in[13];
    float* out = (float*)d_out;

    const int GEMM1_SMEM = 128 * 132 * 4;                       /* 67584 */
    const int GEMM2_SMEM = 4 * 128 * BKP * 2 + 32 * 132 * 4;    /* 57856 */

    cudaFuncSetAttribute(conv_fft_kernel, cudaFuncAttributeMaxDynamicSharedMemorySize, FFT_SMEM);
    cudaFuncSetAttribute(hf_kernel,       cudaFuncAttributeMaxDynamicSharedMemorySize, FFT_SMEM);
    cudaFuncSetAttribute(mma_gemm_kernel,    cudaFuncAttributeMaxDynamicSharedMemorySize, GEMM1_SMEM);
    cudaFuncSetAttribute(mma_gemm_ta_kernel, cudaFuncAttributeMaxDynamicSharedMemorySize, GEMM2_SMEM);

    __nv_bfloat16 *pW1hi, *pW1lo, *pW2hi, *pW2lo;
    cudaGetSymbolAddress((void**)&pW1hi, g_W1hi);
    cudaGetSymbolAddress((void**)&pW1lo, g_W1lo);
    cudaGetSymbolAddress((void**)&pW2hi, g_W2hi);
    cudaGetSymbolAddress((void**)&pW2lo, g_W2lo);
    float *pV, *pG0, *pG1, *pGatedT;
    cudaGetSymbolAddress((void**)&pV,      g_v);
    cudaGetSymbolAddress((void**)&pG0,     g_g0);
    cudaGetSymbolAddress((void**)&pG1,     g_g1);
    cudaGetSymbolAddress((void**)&pGatedT, g_gatedT);

    const int M = BATCH * LSEQ;

    /* launch order puts GEMM1 in the slot ncu captures (was sact_kernel) */
    init_tables_kernel<<<(8193 + 255) / 256, 256>>>();
    split_bf16_kernel<<<(768 * 256 / 4 + 255) / 256, 256>>>(in_W, pW1hi, pW1lo, 768 * 256);
    split_bf16_kernel<<<(256 * 256 / 4 + 255) / 256, 256>>>(out_W, pW2hi, pW2lo, 256 * 256);

    /* in-proj: epilogue writes v/g0/g1 transposed into [b][d][l] */
    mma_gemm_kernel<<<dim3(768 / 128, M / 128), 256, GEMM1_SMEM>>>(
        x, pW1hi, pW1lo, in_b, pV, pG0, pG1, M, 768, 256);

    sact_kernel<<<(64 * LSEQ + 255) / 256, 256>>>(t, mlp_W1, mlp_b1);
    hmix_kernel<<<LSEQ / 128, 128>>>(mlp_W2, mlp_b2);
    hf_kernel<<<DM, FFT_THREADS, FFT_SMEM>>>();

    /* FFT long conv + fused dwconv gating -> gatedT[b][d][l] */
    conv_fft_kernel<<<BATCH * DM, FFT_THREADS, FFT_SMEM>>>(
        pV, pG0, pG1, conv0_W, conv0_b, conv1_W, conv1_b, pGatedT);

    /* out-proj, A transposed */
    mma_gemm_ta_kernel<<<dim3(256 / 128, M / 128), 256, GEMM2_SMEM>>>(
        pGatedT, pW2hi, pW2lo, out_b, out, M, 256, 256);

    (void)in_sizes; (void)n_in; (void)out_size;
}

// round 15
// speedup vs baseline: 1.0639x; 1.0639x over previous
#include <cuda_runtime.h>
#include <cuda_bf16.h>
#include <cuda_fp16.h>
#include <math.h>
#include <stdint.h>

#define BATCH 8
#define DM    256
#define LSEQ  8192
#define NF    8192      /* complex FFT size (for 16384-point real FFT) */
#define FFT_THREADS 512
#define BKP   40        /* padded 16-bit row stride in GEMM smem tiles */
#define FFT_SMEM ((NF + NF / 16) * 8)   /* padded float2 array: 69632 B */

/* ---------------- scratch (device globals; no allocation allowed) ---------------- */
__device__ float2 g_tw8k[4096];                 /* exp(-2pi i j/8192), j<4096   */
__device__ float2 g_u16[8193];                  /* exp(-2pi i k/16384), k<=8192 */
__device__ float  g_sactT[64 * LSEQ];           /* silu(t*W1+b1)^T [64][L]     */
__device__ float  g_h[DM * LSEQ];               /* implicit filter [D][L]      */
__device__ float2 g_Hf[DM * 8193];              /* rfft16384(filter)/16384     */
__device__ __half g_W1h[768 * 256];             /* in_W fp16 (2-MMA scheme)    */
__device__ __nv_bfloat16 g_W2hi[256 * 256];
__device__ __nv_bfloat16 g_W2lo[256 * 256];
__device__ float  g_v [(size_t)BATCH * DM * LSEQ];
__device__ float  g_g0[(size_t)BATCH * DM * LSEQ];
__device__ float  g_g1[(size_t)BATCH * DM * LSEQ];
__device__ float  g_gatedT[(size_t)BATCH * DM * LSEQ];  /* gated, [b][d][l] */

/* ---------------- helpers ---------------- */
__device__ __forceinline__ float2 cmul(float2 a, float2 b) {
    return make_float2(a.x * b.x - a.y * b.y, a.x * b.y + a.y * b.x);
}
__device__ __forceinline__ float2 cmulc(float2 a, float2 w) { /* a * conj(w) */
    return make_float2(a.x * w.x + a.y * w.y, a.y * w.x - a.x * w.y);
}
/* padded smem index: 1 float2 pad per 16 -> low-stride stages drop 4-way conflicts */
__device__ __forceinline__ int IDX(int n) { return n + (n >> 4); }

/* storage position of frequency bin k after radix-4(x6)+radix-2 DIF */
__device__ __forceinline__ int perm13(int k) {
    unsigned v = __brev((unsigned)k) >> 19;
    unsigned w = v >> 1;
    unsigned r = ((w & 0xAAAu) >> 1) | ((w & 0x555u) << 1);
    return (int)((r << 1) | (v & 1u));
}

/* ---------------- table init (idempotent, runs every launch) ---------------- */
__global__ void init_tables_kernel() {
    int i = blockIdx.x * blockDim.x + threadIdx.x;
    if (i < 4096) {
        double a = -2.0 * M_PI * (double)i / 8192.0;
        double s, c; sincos(a, &s, &c);
        g_tw8k[i] = make_float2((float)c, (float)s);
    }
    if (i < 8193) {
        double a = -2.0 * M_PI * (double)i / 16384.0;
        double s, c; sincos(a, &s, &c);
        g_u16[i] = make_float2((float)c, (float)s);
    }
}

/* ---------------- fp32 -> bf16 hi/lo split (W2) ---------------- */
__global__ void split_bf16_kernel(const float* __restrict__ in,
                                  __nv_bfloat16* __restrict__ hi,
                                  __nv_bfloat16* __restrict__ lo, int n) {
    int i = 4 * (blockIdx.x * blockDim.x + threadIdx.x);
    if (i < n) {
        float4 v = *(const float4*)&in[i];
        __nv_bfloat16 h0 = __float2bfloat16_rn(v.x);
        __nv_bfloat16 h1 = __float2bfloat16_rn(v.y);
        __nv_bfloat16 h2 = __float2bfloat16_rn(v.z);
        __nv_bfloat16 h3 = __float2bfloat16_rn(v.w);
        __nv_bfloat162 ph01; ph01.x = h0; ph01.y = h1;
        __nv_bfloat162 ph23; ph23.x = h2; ph23.y = h3;
        *(__nv_bfloat162*)&hi[i]     = ph01;
        *(__nv_bfloat162*)&hi[i + 2] = ph23;
        __nv_bfloat162 pl01, pl23;
        pl01.x = __float2bfloat16_rn(v.x - __bfloat162float(h0));
        pl01.y = __float2bfloat16_rn(v.y - __bfloat162float(h1));
        pl23.x = __float2bfloat16_rn(v.z - __bfloat162float(h2));
        pl23.y = __float2bfloat16_rn(v.w - __bfloat162float(h3));
        *(__nv_bfloat162*)&lo[i]     = pl01;
        *(__nv_bfloat162*)&lo[i + 2] = pl23;
    }
}

/* ---------------- fp32 -> fp16 (W1, single precision-limb) ---------------- */
__global__ void split_fp16_kernel(const float* __restrict__ in,
                                  __half* __restrict__ hi, int n) {
    int i = 4 * (blockIdx.x * blockDim.x + threadIdx.x);
    if (i < n) {
        float4 v = *(const float4*)&in[i];
        __half2 p01 = __floats2half2_rn(v.x, v.y);
        __half2 p23 = __floats2half2_rn(v.z, v.w);
        *(__half2*)&hi[i]     = p01;
        *(__half2*)&hi[i + 2] = p23;
    }
}

/* ---------------- sactT[m][l] = silu(t[l]*W1[m] + b1[m]) ---------------- */
__global__ void sact_kernel(const float* __restrict__ t, const float* __restrict__ W1,
                            const float* __restrict__ b1) {
    int idx = blockIdx.x * blockDim.x + threadIdx.x;
    if (idx < 64 * LSEQ) {
        int m = idx >> 13, l = idx & (LSEQ - 1);
        float z = t[l] * W1[m] + b1[m];
        g_sactT[idx] = z / (1.0f + expf(-z));
    }
}

/* ---------------- h[d][l] = sum_m sactT[m][l]*W2[d][m] + b2[d] ---------------- */
__global__ void hmix_kernel(const float* __restrict__ W2, const float* __restrict__ b2) {
    __shared__ float s[64][129];
    int l0 = blockIdx.x * 128;
    int tid = threadIdx.x; /* 128 */
    for (int m = 0; m < 64; m++) s[m][tid] = g_sactT[m * LSEQ + l0 + tid];
    __syncthreads();
    for (int d0 = 0; d0 < 256; d0 += 4) {
        float a0 = b2[d0 + 0], a1 = b2[d0 + 1], a2 = b2[d0 + 2], a3 = b2[d0 + 3];
        #pragma unroll
        for (int m = 0; m < 64; m++) {
            float sv = s[m][tid];
            a0 += sv * __ldg(&W2[(d0 + 0) * 64 + m]);
            a1 += sv * __ldg(&W2[(d0 + 1) * 64 + m]);
            a2 += sv * __ldg(&W2[(d0 + 2) * 64 + m]);
            a3 += sv * __ldg(&W2[(d0 + 3) * 64 + m]);
        }
        g_h[(size_t)(d0 + 0) * LSEQ + l0 + tid] = a0;
        g_h[(size_t)(d0 + 1) * LSEQ + l0 + tid] = a1;
        g_h[(size_t)(d0 + 2) * LSEQ + l0 + tid] = a2;
        g_h[(size_t)(d0 + 3) * LSEQ + l0 + tid] = a3;
    }
}

/* -------- in-smem radix-4 FFT (8192-pt complex), 6xR4 + 1xR2, padded layout ----- */
__device__ __forceinline__ void fft8k_dif(float2* zs, int tid) {
    #pragma unroll
    for (int ls = 11; ls >= 1; ls -= 2) {
        int s = 1 << ls;
        for (int j = tid; j < 2048; j += FFT_THREADS) {
            int o = j & (s - 1);
            int base = ((j >> ls) << (ls + 2)) + o;
            int i0 = IDX(base), i1 = IDX(base + s), i2 = IDX(base + 2 * s), i3 = IDX(base + 3 * s);
            float2 a = zs[i0], b = zs[i1], c = zs[i2], d = zs[i3];
            float2 t0 = make_float2(a.x + c.x, a.y + c.y);
            float2 t1 = make_float2(a.x - c.x, a.y - c.y);
            float2 t2 = make_float2(b.x + d.x, b.y + d.y);
            float2 t3 = make_float2(b.y - d.y, -(b.x - d.x));   /* -i(b-d) */
            int twi = o << (11 - ls);
            float2 w1 = g_tw8k[twi];
            float2 w2 = g_tw8k[2 * twi];
            float2 w3 = cmul(w1, w2);
            zs[i0] = make_float2(t0.x + t2.x, t0.y + t2.y);
            zs[i1] = cmul(make_float2(t1.x + t3.x, t1.y + t3.y), w1);
            zs[i2] = cmul(make_float2(t0.x - t2.x, t0.y - t2.y), w2);
            zs[i3] = cmul(make_float2(t1.x - t3.x, t1.y - t3.y), w3);
        }
        __syncthreads();
    }
    for (int j = tid; j < 4096; j += FFT_THREADS) {
        int i0 = IDX(2 * j);     /* 2j even -> 2j+1 in same pad block */
        float2 a = zs[i0], b = zs[i0 + 1];
        zs[i0]     = make_float2(a.x + b.x, a.y + b.y);
        zs[i0 + 1] = make_float2(a.x - b.x, a.y - b.y);
    }
    __syncthreads();
}
__device__ __forceinline__ void fft8k_dit_inv(float2* zs, int tid) {
    for (int j = tid; j < 4096; j += FFT_THREADS) {
        int i0 = IDX(2 * j);
        float2 a = zs[i0], b = zs[i0 + 1];
        zs[i0]     = make_float2(a.x + b.x, a.y + b.y);
        zs[i0 + 1] = make_float2(a.x - b.x, a.y - b.y);
    }
    __syncthreads();
    #pragma unroll
    for (int ls = 1; ls <= 11; ls += 2) {
        int s = 1 << ls;
        for (int j = tid; j < 2048; j += FFT_THREADS) {
            int o = j & (s - 1);
            int base = ((j >> ls) << (ls + 2)) + o;
            int i0 = IDX(base), i1 = IDX(base + s), i2 = IDX(base + 2 * s), i3 = IDX(base + 3 * s);
            float2 A = zs[i0], B = zs[i1], C = zs[i2], D = zs[i3];
            int twi = o << (11 - ls);
            float2 w1 = g_tw8k[twi];
            float2 w2 = g_tw8k[2 * twi];
            float2 w3 = cmul(w1, w2);
            float2 u1 = cmulc(B, w1);
            float2 u2 = cmulc(C, w2);
            float2 u3 = cmulc(D, w3);
            float2 s0 = make_float2(A.x + u2.x, A.y + u2.y);
            float2 s1 = make_float2(A.x - u2.x, A.y - u2.y);
            float2 s2 = make_float2(u1.x + u3.x, u1.y + u3.y);
            float2 s3 = make_float2(-(u1.y - u3.y), u1.x - u3.x); /* i(u1-u3) */
            zs[i0] = make_float2(s0.x + s2.x, s0.y + s2.y);
            zs[i1] = make_float2(s1.x + s3.x, s1.y + s3.y);
            zs[i2] = make_float2(s0.x - s2.x, s0.y - s2.y);
            zs[i3] = make_float2(s1.x - s3.x, s1.y - s3.y);
        }
        __syncthreads();
    }
}

/* ---------------- filter FFT (1/16384 folded into Hf) ---------------- */
__global__ void hf_kernel() {
    extern __shared__ float2 zs[];
    int d = blockIdx.x;
    int tid = threadIdx.x;
    const float sc = 1.0f / (float)NF;
    const float2* hr = (const float2*)(g_h + (size_t)d * LSEQ);
    for (int n = tid; n < 4096; n += FFT_THREADS) zs[IDX(n)] = hr[n];
    for (int n = 4096 + tid; n < NF; n += FFT_THREADS) zs[IDX(n)] = make_float2(0.f, 0.f);
    __syncthreads();
    fft8k_dif(zs, tid);
    float2* Hf = g_Hf + (size_t)d * 8193;
    for (int k = tid; k <= 4096; k += FFT_THREADS) {
        if (k == 0) {
            float2 Z0 = zs[0];
            Hf[0]    = make_float2(sc * (Z0.x + Z0.y), 0.f);
            Hf[8192] = make_float2(sc * (Z0.x - Z0.y), 0.f);
        } else if (k == 4096) {
            float2 Z = zs[1]; /* perm13(4096)=1, IDX(1)=1 */
            Hf[4096] = make_float2(sc * Z.x, -sc * Z.y);
        } else {
            float2 Za = zs[IDX(perm13(k))], Zb = zs[IDX(perm13(8192 - k))];
            float2 Xe = make_float2(0.5f * (Za.x + Zb.x), 0.5f * (Za.y - Zb.y));
            float2 dd = make_float2(Za.x - Zb.x, Za.y + Zb.y);
            float2 Xo = make_float2(0.5f * dd.y, -0.5f * dd.x);
            float2 w  = g_u16[k];
            float2 wXo = cmul(w, Xo);
            Hf[k]        = make_float2(sc * (Xe.x + wXo.x), sc * (Xe.y + wXo.y));
            Hf[8192 - k] = make_float2(sc * (Xe.x - wXo.x), -sc * (Xe.y - wXo.y));
        }
    }
}

/* -- conv FFT + fused gating: gatedT[b][d][l] = irfft(rfft(v)*Hf)[:L] * c0 * c1 -- */
__global__ void conv_fft_kernel(const float* __restrict__ v,
                                const float* __restrict__ g0r, const float* __restrict__ g1r,
                                const float* __restrict__ w0, const float* __restrict__ b0,
                                const float* __restrict__ w1, const float* __restrict__ b1,
                                float* __restrict__ gatedT) {
    extern __shared__ float2 zs[];
    int bd = blockIdx.x;
    int d = bd & (DM - 1);
    int tid = threadIdx.x;
    const float2* vr = (const float2*)(v + (size_t)bd * LSEQ);
    for (int n = tid; n < 4096; n += FFT_THREADS) zs[IDX(n)] = vr[n];
    for (int n = 4096 + tid; n < NF; n += FFT_THREADS) zs[IDX(n)] = make_float2(0.f, 0.f);
    __syncthreads();
    fft8k_dif(zs, tid);
    const float2* Hf = g_Hf + (size_t)d * 8193;
    for (int k = tid; k <= 4096; k += FFT_THREADS) {
        if (k == 0) {
            float2 Z0 = zs[0];
            float X0 = Z0.x + Z0.y, XN = Z0.x - Z0.y;
            float2 H0 = Hf[0], HN = Hf[8192];
            float2 P0 = make_float2(X0 * H0.x, X0 * H0.y);
            float2 PN = make_float2(XN * HN.x, XN * HN.y);
            float2 Xe2 = make_float2(0.5f * (P0.x + PN.x), 0.5f * (P0.y - PN.y));
            float2 Xo2 = make_float2(0.5f * (P0.x - PN.x), 0.5f * (P0.y + PN.y));
            zs[0] = make_float2(Xe2.x - Xo2.y, Xe2.y + Xo2.x);
        } else if (k == 4096) {
            float2 Z = zs[1];
            float2 H = Hf[4096];
            zs[1] = make_float2(Z.x * H.x + Z.y * H.y, Z.y * H.x - Z.x * H.y);
        } else {
            int p1 = IDX(perm13(k)), p2 = IDX(perm13(8192 - k));
            float2 Za = zs[p1], Zb = zs[p2];
            float2 Xe = make_float2(0.5f * (Za.x + Zb.x), 0.5f * (Za.y - Zb.y));
            float2 dd = make_float2(Za.x - Zb.x, Za.y + Zb.y);
            float2 Xo = make_float2(0.5f * dd.y, -0.5f * dd.x);
            float2 w  = g_u16[k];
            float2 wXo = cmul(w, Xo);
            float2 Xp = make_float2(Xe.x + wXo.x, Xe.y + wXo.y);
            float2 Xm = make_float2(Xe.x - wXo.x, Xe.y - wXo.y);
            float2 Hk = Hf[k], Hn = Hf[8192 - k];
            float2 P1 = cmul(Xp, Hk);
            float2 Q  = cmul(Xm, make_float2(Hn.x, -Hn.y));
            float2 Xe2 = make_float2(0.5f * (P1.x + Q.x), 0.5f * (P1.y + Q.y));
            float2 pmq = make_float2(P1.x - Q.x, P1.y - Q.y);
            float2 Xo2 = cmul(make_float2(w.x, -w.y), pmq);
            Xo2.x *= 0.5f; Xo2.y *= 0.5f;
            zs[p1] = make_float2(Xe2.x - Xo2.y, Xe2.y + Xo2.x);
            zs[p2] = make_float2(Xe2.x + Xo2.y, Xo2.x - Xe2.y);
        }
    }
    __syncthreads();
    fft8k_dit_inv(zs, tid);

    /* fused dwconv(K=3) gating epilogue. Each thread owns 16 contiguous l.       */
    {
        int l0c = tid * 16;
        size_t rowoff = (size_t)bd * LSEQ + l0c;
        const float* g0p = g0r + rowoff;
        const float* g1p = g1r + rowoff;
        float G0[18], G1[18];
        #pragma unroll
        for (int j = 0; j < 4; j++) {
            float4 q0 = *(const float4*)&g0p[j * 4];
            float4 q1 = *(const float4*)&g1p[j * 4];
            G0[1 + j * 4] = q0.x; G0[2 + j * 4] = q0.y; G0[3 + j * 4] = q0.z; G0[4 + j * 4] = q0.w;
            G1[1 + j * 4] = q1.x; G1[2 + j * 4] = q1.y; G1[3 + j * 4] = q1.z; G1[4 + j * 4] = q1.w;
        }
        G0[0]  = (l0c > 0) ? g0p[-1] : 0.f;
        G1[0]  = (l0c > 0) ? g1p[-1] : 0.f;
        G0[17] = (l0c + 16 < LSEQ) ? g0p[16] : 0.f;
        G1[17] = (l0c + 16 < LSEQ) ? g1p[16] : 0.f;
        float w00 = w0[3 * d], w01 = w0[3 * d + 1], w02 = w0[3 * d + 2], cb0 = b0[d];
        float w10 = w1[3 * d], w11 = w1[3 * d + 1], w12 = w1[3 * d + 2], cb1 = b1[d];
        float Y[16];
        int zb = IDX(tid * 8);   /* 8 consecutive float2, no pad boundary inside */
        #pragma unroll
        for (int j = 0; j < 8; j++) {
            float2 yv = zs[zb + j];
            Y[2 * j] = yv.x; Y[2 * j + 1] = yv.y;
        }
        float O[16];
        #pragma unroll
        for (int i = 0; i < 16; i++) {
            float c0v = w00 * G0[i] + w01 * G0[i + 1] + w02 * G0[i + 2] + cb0;
            float c1v = w10 * G1[i] + w11 * G1[i + 1] + w12 * G1[i + 2] + cb1;
            O[i] = Y[i] * c0v * c1v;
        }
        float* op = gatedT + rowoff;
        #pragma unroll
        for (int j = 0; j < 4; j++) {
            *(float4*)&op[j * 4] = make_float4(O[j * 4], O[j * 4 + 1], O[j * 4 + 2], O[j * 4 + 3]);
        }
    }
}

/* ---------------- tensor-core MMA wrappers ---------------- */
__device__ __forceinline__ void mma_bf16(float c[4], const unsigned a[4],
                                         unsigned b0, unsigned b1) {
    asm volatile(
        "mma.sync.aligned.m16n8k16.row.col.f32.bf16.bf16.f32 "
        "{%0,%1,%2,%3}, {%4,%5,%6,%7}, {%8,%9}, {%0,%1,%2,%3};\n"
        : "+f"(c[0]), "+f"(c[1]), "+f"(c[2]), "+f"(c[3])
        : "r"(a[0]), "r"(a[1]), "r"(a[2]), "r"(a[3]), "r"(b0), "r"(b1));
}
__device__ __forceinline__ void mma_f16(float c[4], const unsigned a[4],
                                        unsigned b0, unsigned b1) {
    asm volatile(
        "mma.sync.aligned.m16n8k16.row.col.f32.f16.f16.f32 "
        "{%0,%1,%2,%3}, {%4,%5,%6,%7}, {%8,%9}, {%0,%1,%2,%3};\n"
        : "+f"(c[0]), "+f"(c[1]), "+f"(c[2]), "+f"(c[3])
        : "r"(a[0]), "r"(a[1]), "r"(a[2]), "r"(a[3]), "r"(b0), "r"(b1));
}

/* GEMM1 (fp16 2-MMA): C = (Ah+Al) @ Wh^T + bias.  A fp32 split to fp16 hi/lo in  */
/* staging; W pre-converted fp16.  128x128 CTA, BK=32, 8 warps, single buffer.    */
/* Transposed epilogue -> v/g0/g1 [b][d][l], bias folded.                         */
__global__ void __launch_bounds__(256) mma_gemm_kernel(
    const float* __restrict__ A,
    const __half* __restrict__ Bh,
    const float* __restrict__ bias,
    float* __restrict__ C0p, float* __restrict__ C1p, float* __restrict__ C2p,
    int M, int N, int K) {
    extern __shared__ char smraw[];
    __half* sAhi = (__half*)smraw;                          /* [128][BKP] */
    __half* sAlo = sAhi + 128 * BKP;
    __half* sBh  = sAlo + 128 * BKP;
    float* ep = (float*)smraw;                              /* [128][132] staging */

    int tid = threadIdx.x;
    int warp = tid >> 5, lane = tid & 31;
    int gid = lane >> 2, tig = lane & 3;
    int warp_m = (warp >> 1) * 32;
    int warp_n = (warp & 1) * 64;
    int m0 = blockIdx.y * 128, n0 = blockIdx.x * 128;
    const float4* gA = (const float4*)A;
    const uint4* gB = (const uint4*)Bh;
    int ldvA = K >> 2;
    int ldvB = K >> 3;

    float acc[2][8][4];
    #pragma unroll
    for (int mt = 0; mt < 2; mt++)
        #pragma unroll
        for (int nt = 0; nt < 8; nt++)
            #pragma unroll
            for (int q = 0; q < 4; q++) acc[mt][nt][q] = 0.f;

    float4 rA[4];
    uint4  rB[2];

    auto load_tile = [&](int k0) {
        int kqa = k0 >> 2, kqb = k0 >> 3;
        #pragma unroll
        for (int i = 0; i < 4; i++) {
            int idx = tid + i * 256;
            int row = idx >> 3, kq = idx & 7;
            rA[i] = gA[(size_t)(m0 + row) * ldvA + kqa + kq];
        }
        #pragma unroll
        for (int i = 0; i < 2; i++) {
            int idx = tid + i * 256;
            int row = idx >> 2, kq = idx & 3;
            rB[i] = gB[(size_t)(n0 + row) * ldvB + kqb + kq];
        }
    };
    auto store_tile = [&]() {
        #pragma unroll
        for (int i = 0; i < 4; i++) {
            int idx = tid + i * 256;
            int row = idx >> 3, kq = idx & 7;
            float4 v = rA[i];
            __half h0 = __float2half_rn(v.x);
            __half h1 = __float2half_rn(v.y);
            __half h2 = __float2half_rn(v.z);
            __half h3 = __float2half_rn(v.w);
            __half2 ph01; ph01.x = h0; ph01.y = h1;
            __half2 ph23; ph23.x = h2; ph23.y = h3;
            int off = row * BKP + kq * 4;
            *(__half2*)&sAhi[off]     = ph01;
            *(__half2*)&sAhi[off + 2] = ph23;
            __half2 pl01, pl23;
            pl01.x = __float2half_rn(v.x - __half2float(h0));
            pl01.y = __float2half_rn(v.y - __half2float(h1));
            pl23.x = __float2half_rn(v.z - __half2float(h2));
            pl23.y = __float2half_rn(v.w - __half2float(h3));
            *(__half2*)&sAlo[off]     = pl01;
            *(__half2*)&sAlo[off + 2] = pl23;
        }
        #pragma unroll
        for (int i = 0; i < 2; i++) {
            int idx = tid + i * 256;
            int row = idx >> 2, kq = idx & 3;
            *(uint4*)&sBh[row * BKP + kq * 8] = rB[i];
        }
    };

    load_tile(0);
    for (int k0 = 0; k0 < K; k0 += 32) {
        __syncthreads();
        store_tile();
        __syncthreads();
        if (k0 + 32 < K) load_tile(k0 + 32);
        #pragma unroll
        for (int k16 = 0; k16 < 32; k16 += 16) {
            unsigned ah[2][4], al[2][4];
            #pragma unroll
            for (int mt = 0; mt < 2; mt++) {
                int base = (warp_m + mt * 16 + gid) * BKP + k16 + 2 * tig;
                ah[mt][0] = *(const unsigned*)&sAhi[base];
                ah[mt][1] = *(const unsigned*)&sAhi[base + 8 * BKP];
                ah[mt][2] = *(const unsigned*)&sAhi[base + 8];
                ah[mt][3] = *(const unsigned*)&sAhi[base + 8 * BKP + 8];
                al[mt][0] = *(const unsigned*)&sAlo[base];
                al[mt][1] = *(const unsigned*)&sAlo[base + 8 * BKP];
                al[mt][2] = *(const unsigned*)&sAlo[base + 8];
                al[mt][3] = *(const unsigned*)&sAlo[base + 8 * BKP + 8];
            }
            #pragma unroll
            for (int nt = 0; nt < 8; nt++) {
                int cbase = (warp_n + nt * 8 + gid) * BKP + k16 + 2 * tig;
                unsigned b0v = *(const unsigned*)&sBh[cbase];
                unsigned b1v = *(const unsigned*)&sBh[cbase + 8];
                #pragma unroll
                for (int mt = 0; mt < 2; mt++) {
                    mma_f16(acc[mt][nt], ah[mt], b0v, b1v);
                    mma_f16(acc[mt][nt], al[mt], b0v, b1v);
                }
            }
        }
    }

    /* transposed epilogue -> v/g0/g1 in [b][d][l] layout, bias folded in */
    __syncthreads();
    #pragma unroll
    for (int mt = 0; mt < 2; mt++) {
        #pragma unroll
        for (int nt = 0; nt < 8; nt++) {
            int rl = warp_m + mt * 16 + gid;
            int cl = warp_n + nt * 8 + 2 * tig;
            ep[(size_t)cl * 132 + rl]           = acc[mt][nt][0];
            ep[(size_t)(cl + 1) * 132 + rl]     = acc[mt][nt][1];
            ep[(size_t)cl * 132 + rl + 8]       = acc[mt][nt][2];
            ep[(size_t)(cl + 1) * 132 + rl + 8] = acc[mt][nt][3];
        }
    }
    __syncthreads();
    int b = m0 >> 13;
    int l0 = m0 & (LSEQ - 1);
    int branch = n0 >> 8;
    int cc0 = n0 & 255;
    float* outp = (branch == 0) ? C0p : ((branch == 1) ? C1p : C2p);
    for (int i = tid; i < 16384; i += 256) {
        int c = i >> 7, l = i & 127;
        outp[((size_t)b * DM + cc0 + c) * LSEQ + l0 + l] = ep[c * 132 + l] + bias[n0 + c];
    }
}

/* GEMM2 (TRANSA, bf16 3-MMA): A stored k-major as At[b][k=d][l].                 */
__global__ void __launch_bounds__(256) mma_gemm_ta_kernel(
    const float* __restrict__ At,
    const __nv_bfloat16* __restrict__ Bhi, const __nv_bfloat16* __restrict__ Blo,
    const float* __restrict__ bias, float* __restrict__ C,
    int M, int N, int K) {
    extern __shared__ char smraw[];
    __nv_bfloat16* sAhi = (__nv_bfloat16*)smraw;            /* [128][BKP] */
    __nv_bfloat16* sAlo = sAhi + 128 * BKP;
    __nv_bfloat16* sBhi = sAlo + 128 * BKP;
    __nv_bfloat16* sBlo = sBhi + 128 * BKP;
    float* sT = (float*)(smraw + 4 * 128 * BKP * 2);        /* [32][132] fp32 */

    int tid = threadIdx.x;
    int warp = tid >> 5, lane = tid & 31;
    int gid = lane >> 2, tig = lane & 3;
    int warp_m = (warp >> 1) * 32;
    int warp_n = (warp & 1) * 64;
    int m0 = blockIdx.y * 128, n0 = blockIdx.x * 128;
    int b = m0 >> 13, l0 = m0 & (LSEQ - 1);
    const uint4* gBh = (const uint4*)Bhi;
    const uint4* gBl = (const uint4*)Blo;
    int ldvB = K >> 3;

    float acc[2][8][4];
    #pragma unroll
    for (int mt = 0; mt < 2; mt++)
        #pragma unroll
        for (int nt = 0; nt < 8; nt++)
            #pragma unroll
            for (int q = 0; q < 4; q++) acc[mt][nt][q] = 0.f;

    float4 rA[4];
    uint4  rBh[2], rBl[2];
    int kkA = tid >> 3, qA = tid & 7;    /* 32 k-rows x 8 threads/row */

    auto load_tile = [&](int k0) {
        const float4* pA = (const float4*)(At + ((size_t)b * DM + k0 + kkA) * LSEQ + l0);
        #pragma unroll
        for (int j = 0; j < 4; j++) rA[j] = pA[qA * 4 + j];
        int kqb = k0 >> 3;
        #pragma unroll
        for (int i = 0; i < 2; i++) {
            int idx = tid + i * 256;
            int row = idx >> 2, kq = idx & 3;
            rBh[i] = gBh[(size_t)(n0 + row) * ldvB + kqb + kq];
            rBl[i] = gBl[(size_t)(n0 + row) * ldvB + kqb + kq];
        }
    };
    auto store_tile = [&]() {
        #pragma unroll
        for (int j = 0; j < 4; j++)
            *(float4*)&sT[kkA * 132 + qA * 16 + j * 4] = rA[j];
        #pragma unroll
        for (int i = 0; i < 2; i++) {
            int idx = tid + i * 256;
            int row = idx >> 2, kq = idx & 3;
            *(uint4*)&sBhi[row * BKP + kq * 8] = rBh[i];
            *(uint4*)&sBlo[row * BKP + kq * 8] = rBl[i];
        }
    };
    auto convert = [&]() {
        int m = tid >> 1, kh = (tid & 1) * 16;
        #pragma unroll
        for (int j = 0; j < 16; j += 2) {
            float v0 = sT[(kh + j) * 132 + m];
            float v1 = sT[(kh + j + 1) * 132 + m];
            __nv_bfloat16 h0 = __float2bfloat16_rn(v0);
            __nv_bfloat16 h1 = __float2bfloat16_rn(v1);
            __nv_bfloat162 ph; ph.x = h0; ph.y = h1;
            *(__nv_bfloat162*)&sAhi[m * BKP + kh + j] = ph;
            __nv_bfloat162 pl;
            pl.x = __float2bfloat16_rn(v0 - __bfloat162float(h0));
            pl.y = __float2bfloat16_rn(v1 - __bfloat162float(h1));
            *(__nv_bfloat162*)&sAlo[m * BKP + kh + j] = pl;
        }
    };

    load_tile(0);
    for (int k0 = 0; k0 < K; k0 += 32) {
        __syncthreads();           /* prev compute done reading sA/sB */
        store_tile();
        __syncthreads();           /* sT/sB visible */
        convert();
        if (k0 + 32 < K) load_tile(k0 + 32);
        __syncthreads();           /* sA visible */
        #pragma unroll
        for (int k16 = 0; k16 < 32; k16 += 16) {
            unsigned ah[2][4], al[2][4];
            #pragma unroll
            for (int mt = 0; mt < 2; mt++) {
                int base = (warp_m + mt * 16 + gid) * BKP + k16 + 2 * tig;
                ah[mt][0] = *(const unsigned*)&sAhi[base];
                ah[mt][1] = *(const unsigned*)&sAhi[base + 8 * BKP];
                ah[mt][2] = *(const unsigned*)&sAhi[base + 8];
                ah[mt][3] = *(const unsigned*)&sAhi[base + 8 * BKP + 8];
                al[mt][0] = *(const unsigned*)&sAlo[base];
                al[mt][1] = *(const unsigned*)&sAlo[base + 8 * BKP];
                al[mt][2] = *(const unsigned*)&sAlo[base + 8];
                al[mt][3] = *(const unsigned*)&sAlo[base + 8 * BKP + 8];
            }
            #pragma unroll
            for (int nt = 0; nt < 8; nt++) {
                int cbase = (warp_n + nt * 8 + gid) * BKP + k16 + 2 * tig;
                unsigned bh0 = *(const unsigned*)&sBhi[cbase];
                unsigned bh1 = *(const unsigned*)&sBhi[cbase + 8];
                unsigned bl0 = *(const unsigned*)&sBlo[cbase];
                unsigned bl1 = *(const unsigned*)&sBlo[cbase + 8];
                #pragma unroll
                for (int mt = 0; mt < 2; mt++) {
                    mma_bf16(acc[mt][nt], ah[mt], bh0, bh1);
                    mma_bf16(acc[mt][nt], ah[mt], bl0, bl1);
                    mma_bf16(acc[mt][nt], al[mt], bh0, bh1);
                }
            }
        }
    }

    #pragma unroll
    for (int mt = 0; mt < 2; mt++) {
        #pragma unroll
        for (int nt = 0; nt < 8; nt++) {
            int r = m0 + warp_m + mt * 16 + gid;
            int c = n0 + warp_n + nt * 8 + 2 * tig;
            float b0v = bias[c], b1v = bias[c + 1];
            float2 w0v = make_float2(acc[mt][nt][0] + b0v, acc[mt][nt][1] + b1v);
            float2 w1v = make_float2(acc[mt][nt][2] + b0v, acc[mt][nt][3] + b1v);
            *(float2*)&C[(size_t)r * N + c] = w0v;
            *(float2*)&C[(size_t)(r + 8) * N + c] = w1v;
        }
    }
}

/* ---------------- launch ---------------- */
extern "C" void kernel_launch(void* const* d_in, const int* in_sizes, int n_in,
                              void* d_out, int out_size) {
    const float* x       = (const float*)d_in[0];
    const float* in_W    = (const float*)d_in[1];
    const float* in_b    = (const float*)d_in[2];
    const float* conv0_W = (const float*)d_in[3];
    const float* conv0_b = (const float*)d_in[4];
    const float* conv1_W = (const float*)d_in[5];
    const float* conv1_b = (const float*)d_in[6];
    const float* mlp_W1  = (const float*)d_in[7];
    const float* mlp_b1  = (const float*)d_in[8];
    const float* mlp_W2  = (const float*)d_in[9];
    const float* mlp_b2  = (const float*)d_in[10];
    const float* out_W   = (const float*)d_in[11];
    const float* out_b   = (const float*)d_in[12];
    const float* t       = (const float*)d_in[13];
    float* out = (float*)d_out;

    const int GEMM1_SMEM = 128 * 132 * 4;                       /* 67584 */
    const int GEMM2_SMEM = 4 * 128 * BKP * 2 + 32 * 132 * 4;    /* 57856 */

    cudaFuncSetAttribute(conv_fft_kernel, cudaFuncAttributeMaxDynamicSharedMemorySize, FFT_SMEM);
    cudaFuncSetAttribute(hf_kernel,       cudaFuncAttributeMaxDynamicSharedMemorySize, FFT_SMEM);
    cudaFuncSetAttribute(mma_gemm_kernel,    cudaFuncAttributeMaxDynamicSharedMemorySize, GEMM1_SMEM);
    cudaFuncSetAttribute(mma_gemm_ta_kernel, cudaFuncAttributeMaxDynamicSharedMemorySize, GEMM2_SMEM);

    __half* pW1h;
    __nv_bfloat16 *pW2hi, *pW2lo;
    cudaGetSymbolAddress((void**)&pW1h,  g_W1h);
    cudaGetSymbolAddress((void**)&pW2hi, g_W2hi);
    cudaGetSymbolAddress((void**)&pW2lo, g_W2lo);
    float *pV, *pG0, *pG1, *pGatedT;
    cudaGetSymbolAddress((void**)&pV,      g_v);
    cudaGetSymbolAddress((void**)&pG0,     g_g0);
    cudaGetSymbolAddress((void**)&pG1,     g_g1);
    cudaGetSymbolAddress((void**)&pGatedT, g_gatedT);

    const int M = BATCH * LSEQ;

    /* launch order keeps GEMM1 in the slot ncu captures */
    init_tables_kernel<<<(8193 + 255) / 256, 256>>>();
    split_fp16_kernel<<<(768 * 256 / 4 + 255) / 256, 256>>>(in_W, pW1h, 768 * 256);
    split_bf16_kernel<<<(256 * 256 / 4 + 255) / 256, 256>>>(out_W, pW2hi, pW2lo, 256 * 256);

    /* in-proj (fp16 2-MMA): epilogue writes v/g0/g1 transposed into [b][d][l] */
    mma_gemm_kernel<<<dim3(768 / 128, M / 128), 256, GEMM1_SMEM>>>(
        x, pW1h, in_b, pV, pG0, pG1, M, 768, 256);

    sact_kernel<<<(64 * LSEQ + 255) / 256, 256>>>(t, mlp_W1, mlp_b1);
    hmix_kernel<<<LSEQ / 128, 128>>>(mlp_W2, mlp_b2);
    hf_kernel<<<DM, FFT_THREADS, FFT_SMEM>>>();

    /* FFT long conv + fused dwconv gating -> gatedT[b][d][l] */
    conv_fft_kernel<<<BATCH * DM, FFT_THREADS, FFT_SMEM>>>(
        pV, pG0, pG1, conv0_W, conv0_b, conv1_W, conv1_b, pGatedT);

    /* out-proj, A transposed (bf16 3-MMA) */
    mma_gemm_ta_kernel<<<dim3(256 / 128, M / 128), 256, GEMM2_SMEM>>>(
        pGatedT, pW2hi, pW2lo, out_b, out, M, 256, 256);

    (void)in_sizes; (void)n_in; (void)out_size;
}

// round 16
// speedup vs baseline: 1.1899x; 1.1185x over previous
#include <cuda_runtime.h>
#include <cuda_bf16.h>
#include <cuda_fp16.h>
#include <math.h>
#include <stdint.h>

#define BATCH 8
#define DM    256
#define LSEQ  8192
#define NF    8192      /* complex FFT size (for 16384-point real FFT) */
#define FFT_THREADS 512
#define BKP   40        /* padded 16-bit row stride in GEMM smem tiles */
#define FFT_SMEM ((NF + NF / 16) * 8)   /* padded float2 array: 69632 B */

/* ---------------- scratch (device globals; no allocation allowed) ---------------- */
__device__ float2 g_tw8k[4096];                 /* exp(-2pi i j/8192), j<4096   */
__device__ float2 g_u16[8193];                  /* exp(-2pi i k/16384), k<=8192 */
__device__ float  g_sactT[64 * LSEQ];           /* silu(t*W1+b1)^T [64][L]     */
__device__ float  g_h[DM * LSEQ];               /* implicit filter [D][L]      */
__device__ float2 g_Hf[DM * 8193];              /* rfft16384(filter)/16384     */
__device__ __half g_W1h[768 * 256];             /* in_W fp16 (2-MMA scheme)    */
__device__ __half g_W2h[256 * 256];             /* out_W fp16 (2-MMA scheme)   */
__device__ float  g_v [(size_t)BATCH * DM * LSEQ];
__device__ float  g_g0[(size_t)BATCH * DM * LSEQ];
__device__ float  g_g1[(size_t)BATCH * DM * LSEQ];
__device__ float  g_gatedT[(size_t)BATCH * DM * LSEQ];  /* gated, [b][d][l] */

/* ---------------- helpers ---------------- */
__device__ __forceinline__ float2 cmul(float2 a, float2 b) {
    return make_float2(a.x * b.x - a.y * b.y, a.x * b.y + a.y * b.x);
}
__device__ __forceinline__ float2 cmulc(float2 a, float2 w) { /* a * conj(w) */
    return make_float2(a.x * w.x + a.y * w.y, a.y * w.x - a.x * w.y);
}
/* padded smem index: 1 float2 pad per 16 -> low-stride stages drop 4-way conflicts */
__device__ __forceinline__ int IDX(int n) { return n + (n >> 4); }

/* storage position of frequency bin k after radix-4(x6)+radix-2 DIF */
__device__ __forceinline__ int perm13(int k) {
    unsigned v = __brev((unsigned)k) >> 19;
    unsigned w = v >> 1;
    unsigned r = ((w & 0xAAAu) >> 1) | ((w & 0x555u) << 1);
    return (int)((r << 1) | (v & 1u));
}

/* ---------------- table init (idempotent, runs every launch) ---------------- */
__global__ void init_tables_kernel() {
    int i = blockIdx.x * blockDim.x + threadIdx.x;
    if (i < 4096) {
        double a = -2.0 * M_PI * (double)i / 8192.0;
        double s, c; sincos(a, &s, &c);
        g_tw8k[i] = make_float2((float)c, (float)s);
    }
    if (i < 8193) {
        double a = -2.0 * M_PI * (double)i / 16384.0;
        double s, c; sincos(a, &s, &c);
        g_u16[i] = make_float2((float)c, (float)s);
    }
}

/* ---------------- fp32 -> fp16 weight conversion ---------------- */
__global__ void split_fp16_kernel(const float* __restrict__ in,
                                  __half* __restrict__ hi, int n) {
    int i = 4 * (blockIdx.x * blockDim.x + threadIdx.x);
    if (i < n) {
        float4 v = *(const float4*)&in[i];
        __half2 p01 = __floats2half2_rn(v.x, v.y);
        __half2 p23 = __floats2half2_rn(v.z, v.w);
        *(__half2*)&hi[i]     = p01;
        *(__half2*)&hi[i + 2] = p23;
    }
}

/* ---------------- sactT[m][l] = silu(t[l]*W1[m] + b1[m]) ---------------- */
__global__ void sact_kernel(const float* __restrict__ t, const float* __restrict__ W1,
                            const float* __restrict__ b1) {
    int idx = blockIdx.x * blockDim.x + threadIdx.x;
    if (idx < 64 * LSEQ) {
        int m = idx >> 13, l = idx & (LSEQ - 1);
        float z = t[l] * W1[m] + b1[m];
        g_sactT[idx] = z / (1.0f + expf(-z));
    }
}

/* ---------------- h[d][l] = sum_m sactT[m][l]*W2[d][m] + b2[d] ---------------- */
__global__ void hmix_kernel(const float* __restrict__ W2, const float* __restrict__ b2) {
    __shared__ float s[64][129];
    int l0 = blockIdx.x * 128;
    int tid = threadIdx.x; /* 128 */
    for (int m = 0; m < 64; m++) s[m][tid] = g_sactT[m * LSEQ + l0 + tid];
    __syncthreads();
    for (int d0 = 0; d0 < 256; d0 += 4) {
        float a0 = b2[d0 + 0], a1 = b2[d0 + 1], a2 = b2[d0 + 2], a3 = b2[d0 + 3];
        #pragma unroll
        for (int m = 0; m < 64; m++) {
            float sv = s[m][tid];
            a0 += sv * __ldg(&W2[(d0 + 0) * 64 + m]);
            a1 += sv * __ldg(&W2[(d0 + 1) * 64 + m]);
            a2 += sv * __ldg(&W2[(d0 + 2) * 64 + m]);
            a3 += sv * __ldg(&W2[(d0 + 3) * 64 + m]);
        }
        g_h[(size_t)(d0 + 0) * LSEQ + l0 + tid] = a0;
        g_h[(size_t)(d0 + 1) * LSEQ + l0 + tid] = a1;
        g_h[(size_t)(d0 + 2) * LSEQ + l0 + tid] = a2;
        g_h[(size_t)(d0 + 3) * LSEQ + l0 + tid] = a3;
    }
}

/* -------- in-smem radix-4 FFT (8192-pt complex), 6xR4 + 1xR2, padded layout ----- */
__device__ __forceinline__ void fft8k_dif(float2* zs, int tid) {
    #pragma unroll
    for (int ls = 11; ls >= 1; ls -= 2) {
        int s = 1 << ls;
        for (int j = tid; j < 2048; j += FFT_THREADS) {
            int o = j & (s - 1);
            int base = ((j >> ls) << (ls + 2)) + o;
            int i0 = IDX(base), i1 = IDX(base + s), i2 = IDX(base + 2 * s), i3 = IDX(base + 3 * s);
            float2 a = zs[i0], b = zs[i1], c = zs[i2], d = zs[i3];
            float2 t0 = make_float2(a.x + c.x, a.y + c.y);
            float2 t1 = make_float2(a.x - c.x, a.y - c.y);
            float2 t2 = make_float2(b.x + d.x, b.y + d.y);
            float2 t3 = make_float2(b.y - d.y, -(b.x - d.x));   /* -i(b-d) */
            int twi = o << (11 - ls);
            float2 w1 = g_tw8k[twi];
            float2 w2 = g_tw8k[2 * twi];
            float2 w3 = cmul(w1, w2);
            zs[i0] = make_float2(t0.x + t2.x, t0.y + t2.y);
            zs[i1] = cmul(make_float2(t1.x + t3.x, t1.y + t3.y), w1);
            zs[i2] = cmul(make_float2(t0.x - t2.x, t0.y - t2.y), w2);
            zs[i3] = cmul(make_float2(t1.x - t3.x, t1.y - t3.y), w3);
        }
        __syncthreads();
    }
    for (int j = tid; j < 4096; j += FFT_THREADS) {
        int i0 = IDX(2 * j);     /* 2j even -> 2j+1 in same pad block */
        float2 a = zs[i0], b = zs[i0 + 1];
        zs[i0]     = make_float2(a.x + b.x, a.y + b.y);
        zs[i0 + 1] = make_float2(a.x - b.x, a.y - b.y);
    }
    __syncthreads();
}
__device__ __forceinline__ void fft8k_dit_inv(float2* zs, int tid) {
    for (int j = tid; j < 4096; j += FFT_THREADS) {
        int i0 = IDX(2 * j);
        float2 a = zs[i0], b = zs[i0 + 1];
        zs[i0]     = make_float2(a.x + b.x, a.y + b.y);
        zs[i0 + 1] = make_float2(a.x - b.x, a.y - b.y);
    }
    __syncthreads();
    #pragma unroll
    for (int ls = 1; ls <= 11; ls += 2) {
        int s = 1 << ls;
        for (int j = tid; j < 2048; j += FFT_THREADS) {
            int o = j & (s - 1);
            int base = ((j >> ls) << (ls + 2)) + o;
            int i0 = IDX(base), i1 = IDX(base + s), i2 = IDX(base + 2 * s), i3 = IDX(base + 3 * s);
            float2 A = zs[i0], B = zs[i1], C = zs[i2], D = zs[i3];
            int twi = o << (11 - ls);
            float2 w1 = g_tw8k[twi];
            float2 w2 = g_tw8k[2 * twi];
            float2 w3 = cmul(w1, w2);
            float2 u1 = cmulc(B, w1);
            float2 u2 = cmulc(C, w2);
            float2 u3 = cmulc(D, w3);
            float2 s0 = make_float2(A.x + u2.x, A.y + u2.y);
            float2 s1 = make_float2(A.x - u2.x, A.y - u2.y);
            float2 s2 = make_float2(u1.x + u3.x, u1.y + u3.y);
            float2 s3 = make_float2(-(u1.y - u3.y), u1.x - u3.x); /* i(u1-u3) */
            zs[i0] = make_float2(s0.x + s2.x, s0.y + s2.y);
            zs[i1] = make_float2(s1.x + s3.x, s1.y + s3.y);
            zs[i2] = make_float2(s0.x - s2.x, s0.y - s2.y);
            zs[i3] = make_float2(s1.x - s3.x, s1.y - s3.y);
        }
        __syncthreads();
    }
}

/* ---------------- filter FFT (1/16384 folded into Hf) ---------------- */
__global__ void hf_kernel() {
    extern __shared__ float2 zs[];
    int d = blockIdx.x;
    int tid = threadIdx.x;
    const float sc = 1.0f / (float)NF;
    const float2* hr = (const float2*)(g_h + (size_t)d * LSEQ);
    for (int n = tid; n < 4096; n += FFT_THREADS) zs[IDX(n)] = hr[n];
    for (int n = 4096 + tid; n < NF; n += FFT_THREADS) zs[IDX(n)] = make_float2(0.f, 0.f);
    __syncthreads();
    fft8k_dif(zs, tid);
    float2* Hf = g_Hf + (size_t)d * 8193;
    for (int k = tid; k <= 4096; k += FFT_THREADS) {
        if (k == 0) {
            float2 Z0 = zs[0];
            Hf[0]    = make_float2(sc * (Z0.x + Z0.y), 0.f);
            Hf[8192] = make_float2(sc * (Z0.x - Z0.y), 0.f);
        } else if (k == 4096) {
            float2 Z = zs[1]; /* perm13(4096)=1, IDX(1)=1 */
            Hf[4096] = make_float2(sc * Z.x, -sc * Z.y);
        } else {
            float2 Za = zs[IDX(perm13(k))], Zb = zs[IDX(perm13(8192 - k))];
            float2 Xe = make_float2(0.5f * (Za.x + Zb.x), 0.5f * (Za.y - Zb.y));
            float2 dd = make_float2(Za.x - Zb.x, Za.y + Zb.y);
            float2 Xo = make_float2(0.5f * dd.y, -0.5f * dd.x);
            float2 w  = g_u16[k];
            float2 wXo = cmul(w, Xo);
            Hf[k]        = make_float2(sc * (Xe.x + wXo.x), sc * (Xe.y + wXo.y));
            Hf[8192 - k] = make_float2(sc * (Xe.x - wXo.x), -sc * (Xe.y - wXo.y));
        }
    }
}

/* -- conv FFT + fused gating: gatedT[b][d][l] = irfft(rfft(v)*Hf)[:L] * c0 * c1 -- */
__global__ void conv_fft_kernel(const float* __restrict__ v,
                                const float* __restrict__ g0r, const float* __restrict__ g1r,
                                const float* __restrict__ w0, const float* __restrict__ b0,
                                const float* __restrict__ w1, const float* __restrict__ b1,
                                float* __restrict__ gatedT) {
    extern __shared__ float2 zs[];
    int bd = blockIdx.x;
    int d = bd & (DM - 1);
    int tid = threadIdx.x;
    const float2* vr = (const float2*)(v + (size_t)bd * LSEQ);
    for (int n = tid; n < 4096; n += FFT_THREADS) zs[IDX(n)] = vr[n];
    for (int n = 4096 + tid; n < NF; n += FFT_THREADS) zs[IDX(n)] = make_float2(0.f, 0.f);
    __syncthreads();
    fft8k_dif(zs, tid);
    const float2* Hf = g_Hf + (size_t)d * 8193;
    for (int k = tid; k <= 4096; k += FFT_THREADS) {
        if (k == 0) {
            float2 Z0 = zs[0];
            float X0 = Z0.x + Z0.y, XN = Z0.x - Z0.y;
            float2 H0 = Hf[0], HN = Hf[8192];
            float2 P0 = make_float2(X0 * H0.x, X0 * H0.y);
            float2 PN = make_float2(XN * HN.x, XN * HN.y);
            float2 Xe2 = make_float2(0.5f * (P0.x + PN.x), 0.5f * (P0.y - PN.y));
            float2 Xo2 = make_float2(0.5f * (P0.x - PN.x), 0.5f * (P0.y + PN.y));
            zs[0] = make_float2(Xe2.x - Xo2.y, Xe2.y + Xo2.x);
        } else if (k == 4096) {
            float2 Z = zs[1];
            float2 H = Hf[4096];
            zs[1] = make_float2(Z.x * H.x + Z.y * H.y, Z.y * H.x - Z.x * H.y);
        } else {
            int p1 = IDX(perm13(k)), p2 = IDX(perm13(8192 - k));
            float2 Za = zs[p1], Zb = zs[p2];
            float2 Xe = make_float2(0.5f * (Za.x + Zb.x), 0.5f * (Za.y - Zb.y));
            float2 dd = make_float2(Za.x - Zb.x, Za.y + Zb.y);
            float2 Xo = make_float2(0.5f * dd.y, -0.5f * dd.x);
            float2 w  = g_u16[k];
            float2 wXo = cmul(w, Xo);
            float2 Xp = make_float2(Xe.x + wXo.x, Xe.y + wXo.y);
            float2 Xm = make_float2(Xe.x - wXo.x, Xe.y - wXo.y);
            float2 Hk = Hf[k], Hn = Hf[8192 - k];
            float2 P1 = cmul(Xp, Hk);
            float2 Q  = cmul(Xm, make_float2(Hn.x, -Hn.y));
            float2 Xe2 = make_float2(0.5f * (P1.x + Q.x), 0.5f * (P1.y + Q.y));
            float2 pmq = make_float2(P1.x - Q.x, P1.y - Q.y);
            float2 Xo2 = cmul(make_float2(w.x, -w.y), pmq);
            Xo2.x *= 0.5f; Xo2.y *= 0.5f;
            zs[p1] = make_float2(Xe2.x - Xo2.y, Xe2.y + Xo2.x);
            zs[p2] = make_float2(Xe2.x + Xo2.y, Xo2.x - Xe2.y);
        }
    }
    __syncthreads();
    fft8k_dit_inv(zs, tid);

    /* fused dwconv(K=3) gating epilogue. Each thread owns 16 contiguous l.       */
    {
        int l0c = tid * 16;
        size_t rowoff = (size_t)bd * LSEQ + l0c;
        const float* g0p = g0r + rowoff;
        const float* g1p = g1r + rowoff;
        float G0[18], G1[18];
        #pragma unroll
        for (int j = 0; j < 4; j++) {
            float4 q0 = *(const float4*)&g0p[j * 4];
            float4 q1 = *(const float4*)&g1p[j * 4];
            G0[1 + j * 4] = q0.x; G0[2 + j * 4] = q0.y; G0[3 + j * 4] = q0.z; G0[4 + j * 4] = q0.w;
            G1[1 + j * 4] = q1.x; G1[2 + j * 4] = q1.y; G1[3 + j * 4] = q1.z; G1[4 + j * 4] = q1.w;
        }
        G0[0]  = (l0c > 0) ? g0p[-1] : 0.f;
        G1[0]  = (l0c > 0) ? g1p[-1] : 0.f;
        G0[17] = (l0c + 16 < LSEQ) ? g0p[16] : 0.f;
        G1[17] = (l0c + 16 < LSEQ) ? g1p[16] : 0.f;
        float w00 = w0[3 * d], w01 = w0[3 * d + 1], w02 = w0[3 * d + 2], cb0 = b0[d];
        float w10 = w1[3 * d], w11 = w1[3 * d + 1], w12 = w1[3 * d + 2], cb1 = b1[d];
        float Y[16];
        int zb = IDX(tid * 8);   /* 8 consecutive float2, no pad boundary inside */
        #pragma unroll
        for (int j = 0; j < 8; j++) {
            float2 yv = zs[zb + j];
            Y[2 * j] = yv.x; Y[2 * j + 1] = yv.y;
        }
        float O[16];
        #pragma unroll
        for (int i = 0; i < 16; i++) {
            float c0v = w00 * G0[i] + w01 * G0[i + 1] + w02 * G0[i + 2] + cb0;
            float c1v = w10 * G1[i] + w11 * G1[i + 1] + w12 * G1[i + 2] + cb1;
            O[i] = Y[i] * c0v * c1v;
        }
        float* op = gatedT + rowoff;
        #pragma unroll
        for (int j = 0; j < 4; j++) {
            *(float4*)&op[j * 4] = make_float4(O[j * 4], O[j * 4 + 1], O[j * 4 + 2], O[j * 4 + 3]);
        }
    }
}

/* ---------------- tensor-core MMA wrapper (fp16) ---------------- */
__device__ __forceinline__ void mma_f16(float c[4], const unsigned a[4],
                                        unsigned b0, unsigned b1) {
    asm volatile(
        "mma.sync.aligned.m16n8k16.row.col.f32.f16.f16.f32 "
        "{%0,%1,%2,%3}, {%4,%5,%6,%7}, {%8,%9}, {%0,%1,%2,%3};\n"
        : "+f"(c[0]), "+f"(c[1]), "+f"(c[2]), "+f"(c[3])
        : "r"(a[0]), "r"(a[1]), "r"(a[2]), "r"(a[3]), "r"(b0), "r"(b1));
}

/* GEMM1 (fp16 2-MMA): C = (Ah+Al) @ Wh^T + bias.  A fp32 split to fp16 hi/lo in  */
/* staging; W pre-converted fp16.  128x128 CTA, BK=32, 8 warps, single buffer.    */
/* launch_bounds(256,2) caps regs at 128 so 2 CTAs/SM stay resident.              */
__global__ void __launch_bounds__(256, 2) mma_gemm_kernel(
    const float* __restrict__ A,
    const __half* __restrict__ Bh,
    const float* __restrict__ bias,
    float* __restrict__ C0p, float* __restrict__ C1p, float* __restrict__ C2p,
    int M, int N, int K) {
    extern __shared__ char smraw[];
    __half* sAhi = (__half*)smraw;                          /* [128][BKP] */
    __half* sAlo = sAhi + 128 * BKP;
    __half* sBh  = sAlo + 128 * BKP;
    float* ep = (float*)smraw;                              /* [128][132] staging */

    int tid = threadIdx.x;
    int warp = tid >> 5, lane = tid & 31;
    int gid = lane >> 2, tig = lane & 3;
    int warp_m = (warp >> 1) * 32;
    int warp_n = (warp & 1) * 64;
    int m0 = blockIdx.y * 128, n0 = blockIdx.x * 128;
    const float4* gA = (const float4*)A;
    const uint4* gB = (const uint4*)Bh;
    int ldvA = K >> 2;
    int ldvB = K >> 3;

    float acc[2][8][4];
    #pragma unroll
    for (int mt = 0; mt < 2; mt++)
        #pragma unroll
        for (int nt = 0; nt < 8; nt++)
            #pragma unroll
            for (int q = 0; q < 4; q++) acc[mt][nt][q] = 0.f;

    float4 rA[4];
    uint4  rB[2];

    auto load_tile = [&](int k0) {
        int kqa = k0 >> 2, kqb = k0 >> 3;
        #pragma unroll
        for (int i = 0; i < 4; i++) {
            int idx = tid + i * 256;
            int row = idx >> 3, kq = idx & 7;
            rA[i] = gA[(size_t)(m0 + row) * ldvA + kqa + kq];
        }
        #pragma unroll
        for (int i = 0; i < 2; i++) {
            int idx = tid + i * 256;
            int row = idx >> 2, kq = idx & 3;
            rB[i] = gB[(size_t)(n0 + row) * ldvB + kqb + kq];
        }
    };
    auto store_tile = [&]() {
        #pragma unroll
        for (int i = 0; i < 4; i++) {
            int idx = tid + i * 256;
            int row = idx >> 3, kq = idx & 7;
            float4 v = rA[i];
            __half h0 = __float2half_rn(v.x);
            __half h1 = __float2half_rn(v.y);
            __half h2 = __float2half_rn(v.z);
            __half h3 = __float2half_rn(v.w);
            __half2 ph01; ph01.x = h0; ph01.y = h1;
            __half2 ph23; ph23.x = h2; ph23.y = h3;
            int off = row * BKP + kq * 4;
            *(__half2*)&sAhi[off]     = ph01;
            *(__half2*)&sAhi[off + 2] = ph23;
            __half2 pl01, pl23;
            pl01.x = __float2half_rn(v.x - __half2float(h0));
            pl01.y = __float2half_rn(v.y - __half2float(h1));
            pl23.x = __float2half_rn(v.z - __half2float(h2));
            pl23.y = __float2half_rn(v.w - __half2float(h3));
            *(__half2*)&sAlo[off]     = pl01;
            *(__half2*)&sAlo[off + 2] = pl23;
        }
        #pragma unroll
        for (int i = 0; i < 2; i++) {
            int idx = tid + i * 256;
            int row = idx >> 2, kq = idx & 3;
            *(uint4*)&sBh[row * BKP + kq * 8] = rB[i];
        }
    };

    load_tile(0);
    for (int k0 = 0; k0 < K; k0 += 32) {
        __syncthreads();
        store_tile();
        __syncthreads();
        if (k0 + 32 < K) load_tile(k0 + 32);
        #pragma unroll
        for (int k16 = 0; k16 < 32; k16 += 16) {
            unsigned ah[2][4], al[2][4];
            #pragma unroll
            for (int mt = 0; mt < 2; mt++) {
                int base = (warp_m + mt * 16 + gid) * BKP + k16 + 2 * tig;
                ah[mt][0] = *(const unsigned*)&sAhi[base];
                ah[mt][1] = *(const unsigned*)&sAhi[base + 8 * BKP];
                ah[mt][2] = *(const unsigned*)&sAhi[base + 8];
                ah[mt][3] = *(const unsigned*)&sAhi[base + 8 * BKP + 8];
                al[mt][0] = *(const unsigned*)&sAlo[base];
                al[mt][1] = *(const unsigned*)&sAlo[base + 8 * BKP];
                al[mt][2] = *(const unsigned*)&sAlo[base + 8];
                al[mt][3] = *(const unsigned*)&sAlo[base + 8 * BKP + 8];
            }
            #pragma unroll
            for (int nt = 0; nt < 8; nt++) {
                int cbase = (warp_n + nt * 8 + gid) * BKP + k16 + 2 * tig;
                unsigned b0v = *(const unsigned*)&sBh[cbase];
                unsigned b1v = *(const unsigned*)&sBh[cbase + 8];
                #pragma unroll
                for (int mt = 0; mt < 2; mt++) {
                    mma_f16(acc[mt][nt], ah[mt], b0v, b1v);
                    mma_f16(acc[mt][nt], al[mt], b0v, b1v);
                }
            }
        }
    }

    /* transposed epilogue -> v/g0/g1 in [b][d][l] layout, bias folded in */
    __syncthreads();
    #pragma unroll
    for (int mt = 0; mt < 2; mt++) {
        #pragma unroll
        for (int nt = 0; nt < 8; nt++) {
            int rl = warp_m + mt * 16 + gid;
            int cl = warp_n + nt * 8 + 2 * tig;
            ep[(size_t)cl * 132 + rl]           = acc[mt][nt][0];
            ep[(size_t)(cl + 1) * 132 + rl]     = acc[mt][nt][1];
            ep[(size_t)cl * 132 + rl + 8]       = acc[mt][nt][2];
            ep[(size_t)(cl + 1) * 132 + rl + 8] = acc[mt][nt][3];
        }
    }
    __syncthreads();
    int b = m0 >> 13;
    int l0 = m0 & (LSEQ - 1);
    int branch = n0 >> 8;
    int cc0 = n0 & 255;
    float* outp = (branch == 0) ? C0p : ((branch == 1) ? C1p : C2p);
    for (int i = tid; i < 16384; i += 256) {
        int c = i >> 7, l = i & 127;
        outp[((size_t)b * DM + cc0 + c) * LSEQ + l0 + l] = ep[c * 132 + l] + bias[n0 + c];
    }
}

/* GEMM2 (TRANSA, fp16 2-MMA, 1/16 scale guard): A k-major At[b][k=d][l].         */
/* Staging: sT fp32 -> transpose+scale(2^-4)+fp16 hi/lo.  C = 16*acc + bias.      */
__global__ void __launch_bounds__(256, 2) mma_gemm_ta_kernel(
    const float* __restrict__ At,
    const __half* __restrict__ Bh,
    const float* __restrict__ bias, float* __restrict__ C,
    int M, int N, int K) {
    extern __shared__ char smraw[];
    __half* sAhi = (__half*)smraw;                          /* [128][BKP] */
    __half* sAlo = sAhi + 128 * BKP;
    __half* sBh  = sAlo + 128 * BKP;
    float* sT = (float*)(smraw + 3 * 128 * BKP * 2);        /* [32][132] fp32 */

    int tid = threadIdx.x;
    int warp = tid >> 5, lane = tid & 31;
    int gid = lane >> 2, tig = lane & 3;
    int warp_m = (warp >> 1) * 32;
    int warp_n = (warp & 1) * 64;
    int m0 = blockIdx.y * 128, n0 = blockIdx.x * 128;
    int b = m0 >> 13, l0 = m0 & (LSEQ - 1);
    const uint4* gB = (const uint4*)Bh;
    int ldvB = K >> 3;
    const float SC = 0.0625f;           /* 2^-4 range guard (exact) */

    float acc[2][8][4];
    #pragma unroll
    for (int mt = 0; mt < 2; mt++)
        #pragma unroll
        for (int nt = 0; nt < 8; nt++)
            #pragma unroll
            for (int q = 0; q < 4; q++) acc[mt][nt][q] = 0.f;

    float4 rA[4];
    uint4  rB[2];
    int kkA = tid >> 3, qA = tid & 7;    /* 32 k-rows x 8 threads/row */

    auto load_tile = [&](int k0) {
        const float4* pA = (const float4*)(At + ((size_t)b * DM + k0 + kkA) * LSEQ + l0);
        #pragma unroll
        for (int j = 0; j < 4; j++) rA[j] = pA[qA * 4 + j];
        int kqb = k0 >> 3;
        #pragma unroll
        for (int i = 0; i < 2; i++) {
            int idx = tid + i * 256;
            int row = idx >> 2, kq = idx & 3;
            rB[i] = gB[(size_t)(n0 + row) * ldvB + kqb + kq];
        }
    };
    auto store_tile = [&]() {
        #pragma unroll
        for (int j = 0; j < 4; j++)
            *(float4*)&sT[kkA * 132 + qA * 16 + j * 4] = rA[j];
        #pragma unroll
        for (int i = 0; i < 2; i++) {
            int idx = tid + i * 256;
            int row = idx >> 2, kq = idx & 3;
            *(uint4*)&sBh[row * BKP + kq * 8] = rB[i];
        }
    };
    auto convert = [&]() {
        int m = tid >> 1, kh = (tid & 1) * 16;
        #pragma unroll
        for (int j = 0; j < 16; j += 2) {
            float v0 = sT[(kh + j) * 132 + m] * SC;
            float v1 = sT[(kh + j + 1) * 132 + m] * SC;
            __half h0 = __float2half_rn(v0);
            __half h1 = __float2half_rn(v1);
            __half2 ph; ph.x = h0; ph.y = h1;
            *(__half2*)&sAhi[m * BKP + kh + j] = ph;
            __half2 pl;
            pl.x = __float2half_rn(v0 - __half2float(h0));
            pl.y = __float2half_rn(v1 - __half2float(h1));
            *(__half2*)&sAlo[m * BKP + kh + j] = pl;
        }
    };

    load_tile(0);
    for (int k0 = 0; k0 < K; k0 += 32) {
        __syncthreads();           /* prev compute done reading sA/sB */
        store_tile();
        __syncthreads();           /* sT/sB visible */
        convert();
        if (k0 + 32 < K) load_tile(k0 + 32);
        __syncthreads();           /* sA visible */
        #pragma unroll
        for (int k16 = 0; k16 < 32; k16 += 16) {
            unsigned ah[2][4], al[2][4];
            #pragma unroll
            for (int mt = 0; mt < 2; mt++) {
                int base = (warp_m + mt * 16 + gid) * BKP + k16 + 2 * tig;
                ah[mt][0] = *(const unsigned*)&sAhi[base];
                ah[mt][1] = *(const unsigned*)&sAhi[base + 8 * BKP];
                ah[mt][2] = *(const unsigned*)&sAhi[base + 8];
                ah[mt][3] = *(const unsigned*)&sAhi[base + 8 * BKP + 8];
                al[mt][0] = *(const unsigned*)&sAlo[base];
                al[mt][1] = *(const unsigned*)&sAlo[base + 8 * BKP];
                al[mt][2] = *(const unsigned*)&sAlo[base + 8];
                al[mt][3] = *(const unsigned*)&sAlo[base + 8 * BKP + 8];
            }
            #pragma unroll
            for (int nt = 0; nt < 8; nt++) {
                int cbase = (warp_n + nt * 8 + gid) * BKP + k16 + 2 * tig;
                unsigned b0v = *(const unsigned*)&sBh[cbase];
                unsigned b1v = *(const unsigned*)&sBh[cbase + 8];
                #pragma unroll
                for (int mt = 0; mt < 2; mt++) {
                    mma_f16(acc[mt][nt], ah[mt], b0v, b1v);
                    mma_f16(acc[mt][nt], al[mt], b0v, b1v);
                }
            }
        }
    }

    #pragma unroll
    for (int mt = 0; mt < 2; mt++) {
        #pragma unroll
        for (int nt = 0; nt < 8; nt++) {
            int r = m0 + warp_m + mt * 16 + gid;
            int c = n0 + warp_n + nt * 8 + 2 * tig;
            float b0v = bias[c], b1v = bias[c + 1];
            float2 w0v = make_float2(acc[mt][nt][0] * 16.f + b0v, acc[mt][nt][1] * 16.f + b1v);
            float2 w1v = make_float2(acc[mt][nt][2] * 16.f + b0v, acc[mt][nt][3] * 16.f + b1v);
            *(float2*)&C[(size_t)r * N + c] = w0v;
            *(float2*)&C[(size_t)(r + 8) * N + c] = w1v;
        }
    }
}

/* ---------------- launch ---------------- */
extern "C" void kernel_launch(void* const* d_in, const int* in_sizes, int n_in,
                              void* d_out, int out_size) {
    const float* x       = (const float*)d_in[0];
    const float* in_W    = (const float*)d_in[1];
    const float* in_b    = (const float*)d_in[2];
    const float* conv0_W = (const float*)d_in[3];
    const float* conv0_b = (const float*)d_in[4];
    const float* conv1_W = (const float*)d_in[5];
    const float* conv1_b = (const float*)d_in[6];
    const float* mlp_W1  = (const float*)d_in[7];
    const float* mlp_b1  = (const float*)d_in[8];
    const float* mlp_W2  = (const float*)d_in[9];
    const float* mlp_b2  = (const float*)d_in[10];
    const float* out_W   = (const float*)d_in[11];
    const float* out_b   = (const float*)d_in[12];
    const float* t       = (const float*)d_in[13];
    float* out = (float*)d_out;

    const int GEMM1_SMEM = 128 * 132 * 4;                       /* 67584 */
    const int GEMM2_SMEM = 3 * 128 * BKP * 2 + 32 * 132 * 4;    /* 47616 */

    cudaFuncSetAttribute(conv_fft_kernel, cudaFuncAttributeMaxDynamicSharedMemorySize, FFT_SMEM);
    cudaFuncSetAttribute(hf_kernel,       cudaFuncAttributeMaxDynamicSharedMemorySize, FFT_SMEM);
    cudaFuncSetAttribute(mma_gemm_kernel,    cudaFuncAttributeMaxDynamicSharedMemorySize, GEMM1_SMEM);
    cudaFuncSetAttribute(mma_gemm_ta_kernel, cudaFuncAttributeMaxDynamicSharedMemorySize, GEMM2_SMEM);

    __half *pW1h, *pW2h;
    cudaGetSymbolAddress((void**)&pW1h, g_W1h);
    cudaGetSymbolAddress((void**)&pW2h, g_W2h);
    float *pV, *pG0, *pG1, *pGatedT;
    cudaGetSymbolAddress((void**)&pV,      g_v);
    cudaGetSymbolAddress((void**)&pG0,     g_g0);
    cudaGetSymbolAddress((void**)&pG1,     g_g1);
    cudaGetSymbolAddress((void**)&pGatedT, g_gatedT);

    const int M = BATCH * LSEQ;

    /* launch order keeps GEMM1 in the slot ncu captures */
    init_tables_kernel<<<(8193 + 255) / 256, 256>>>();
    split_fp16_kernel<<<(768 * 256 / 4 + 255) / 256, 256>>>(in_W, pW1h, 768 * 256);
    split_fp16_kernel<<<(256 * 256 / 4 + 255) / 256, 256>>>(out_W, pW2h, 256 * 256);

    /* in-proj (fp16 2-MMA): epilogue writes v/g0/g1 transposed into [b][d][l] */
    mma_gemm_kernel<<<dim3(768 / 128, M / 128), 256, GEMM1_SMEM>>>(
        x, pW1h, in_b, pV, pG0, pG1, M, 768, 256);

    sact_kernel<<<(64 * LSEQ + 255) / 256, 256>>>(t, mlp_W1, mlp_b1);
    hmix_kernel<<<LSEQ / 128, 128>>>(mlp_W2, mlp_b2);
    hf_kernel<<<DM, FFT_THREADS, FFT_SMEM>>>();

    /* FFT long conv + fused dwconv gating -> gatedT[b][d][l] */
    conv_fft_kernel<<<BATCH * DM, FFT_THREADS, FFT_SMEM>>>(
        pV, pG0, pG1, conv0_W, conv0_b, conv1_W, conv1_b, pGatedT);

    /* out-proj, A transposed (fp16 2-MMA, scale guard) */
    mma_gemm_ta_kernel<<<dim3(256 / 128, M / 128), 256, GEMM2_SMEM>>>(
        pGatedT, pW2h, out_b, out, M, 256, 256);

    (void)in_sizes; (void)n_in; (void)out_size;
}